// round 5
// baseline (speedup 1.0000x reference)
#include <cuda_runtime.h>

#define D_ 6
#define N_ 32768
#define K_ 16
#define DIN_ 64
#define DOUT_ 64

typedef unsigned long long u64;

// SoA ping-pong state. {h,c} packed per (row, dim-pair) as ulonglong2 (16B),
// G separate u64. Row 0 = zero row for masked children: .bss zero, never written.
__device__ ulonglong2 g_hc[2][(N_ + 1) * 32];
__device__ u64 g_G2[2][(N_ + 1) * 32];   // G = 0.5 * (h @ U_f), pre-halved
// Precomputed Wx for all depths: [6*N][256], cols = [f | i | u | o]
__device__ float g_Wx[(size_t)D_ * N_ * 4 * DOUT_];

#define HALF2 0x3F0000003F000000ULL   // {0.5f, 0.5f}

__device__ __forceinline__ u64 pk2(float lo, float hi) {
    u64 r; asm("mov.b64 %0, {%1,%2};" : "=l"(r) : "f"(lo), "f"(hi)); return r;
}
__device__ __forceinline__ void upk2(u64 v, float& lo, float& hi) {
    asm("mov.b64 {%0,%1}, %2;" : "=f"(lo), "=f"(hi) : "l"(v));
}
__device__ __forceinline__ u64 fma2_(u64 a, u64 b, u64 c) {
    u64 d; asm("fma.rn.f32x2 %0, %1, %2, %3;" : "=l"(d) : "l"(a), "l"(b), "l"(c)); return d;
}
__device__ __forceinline__ u64 add2_(u64 a, u64 b) {
    u64 d; asm("add.rn.f32x2 %0, %1, %2;" : "=l"(d) : "l"(a), "l"(b)); return d;
}
__device__ __forceinline__ u64 mul2_(u64 a, u64 b) {
    u64 d; asm("mul.rn.f32x2 %0, %1, %2;" : "=l"(d) : "l"(a), "l"(b)); return d;
}
__device__ __forceinline__ float tanha(float x) {
    float y; asm("tanh.approx.f32 %0, %1;" : "=f"(y) : "f"(x)); return y;
}
// sigmoid(2*arg) given arg pre-halved: 0.5*tanh(arg)+0.5, packed
__device__ __forceinline__ u64 sig2h(u64 argHalf) {
    float a, b; upk2(argHalf, a, b);
    return fma2_(pk2(tanha(a), tanha(b)), HALF2, HALF2);
}
__device__ __forceinline__ u64 tanh2(u64 v) {
    float a, b; upk2(v, a, b);
    return pk2(tanha(a), tanha(b));
}

// Wx[n][q] = E[labels[n]] @ W_w + W_b, f32x2 over d-pairs.
__global__ __launch_bounds__(256) void wx_kernel(const int* __restrict__ labels,
                                                 const float* __restrict__ E,
                                                 const float* __restrict__ Ww,
                                                 const float* __restrict__ Wb) {
    __shared__ u64 xs2[64 * 32];
    __shared__ int lab_s[64];
    int t = threadIdx.x;
    int base = blockIdx.x * 64;
    if (t < 64) lab_s[t] = labels[base + t];
    __syncthreads();
    for (int e = t; e < 64 * 32; e += 256) {
        int i = e >> 5, d2 = e & 31;
        float2 v = reinterpret_cast<const float2*>(E + (size_t)lab_s[i] * DIN_)[d2];
        xs2[e] = pk2(v.x, v.y);
    }
    u64 w2[32];
#pragma unroll
    for (int d2 = 0; d2 < 32; d2++)
        w2[d2] = pk2(Ww[(2 * d2) * 256 + t], Ww[(2 * d2 + 1) * 256 + t]);
    float b = Wb[t];
    __syncthreads();
    for (int i = 0; i < 64; i++) {
        const u64* x = xs2 + (i << 5);
        u64 a = 0;
#pragma unroll
        for (int d2 = 0; d2 < 32; d2++) a = fma2_(x[d2], w2[d2], a);
        float l, h; upk2(a, l, h);
        g_Wx[(size_t)(base + i) * 256 + t] = b + l + h;
    }
}

// Warp-synchronous depth step: 4 nodes/warp, packed f32x2 math,
// smem-broadcast matvecs (no shfl in the hot loops), LDG.128 gather.
__global__ __launch_bounds__(256, 3) void node_kernel(const int* __restrict__ child_idx,
                                                      const float* __restrict__ Uf,
                                                      const float* __restrict__ Uiuo,
                                                      float* __restrict__ out,
                                                      int depth) {
    const int rb = depth & 1, wb = rb ^ 1;
    const ulonglong2* __restrict__ hcp = g_hc[rb];
    const u64* __restrict__ Gp = g_G2[rb];
    ulonglong2* __restrict__ hcn = g_hc[wb];
    u64* __restrict__ Gn = g_G2[wb];

    extern __shared__ u64 smu[];
    // U2: [32 sl][3 m][32 lane][2 par] ; par: d=2sl (even), d=2sl+1 (odd)
    u64* U2  = smu;                 // 6144 u64 = 48KB
    // Uf2: [32 sl][32 lane][2 par], pre-scaled by 0.5
    u64* Uf2 = smu + 6144;          // 2048 u64 = 16KB
    // per-warp broadcast buffers: [8 warps][32 lanes][4 q]
    u64* HB  = smu + 8192;          // 1024 u64 = 8KB

    int tid = threadIdx.x;
    for (int e = tid; e < 6144; e += 256) {
        int par = e & 1, lane = (e >> 1) & 31, m = (e >> 6) % 3, sl = e / 192;
        int d = 2 * sl + par, col = m * 64 + 2 * lane;
        U2[e] = pk2(Uiuo[d * 192 + col], Uiuo[d * 192 + col + 1]);
    }
    for (int e = tid; e < 2048; e += 256) {
        int par = e & 1, lane = (e >> 1) & 31, sl = e >> 6;
        int d = 2 * sl + par;
        Uf2[e] = pk2(0.5f * Uf[d * 64 + 2 * lane], 0.5f * Uf[d * 64 + 2 * lane + 1]);
    }
    __syncthreads();   // only block barrier

    const int lane = tid & 31;
    ulonglong2* hb2 = reinterpret_cast<ulonglong2*>(HB + (tid >> 5) * 128);
    const int gwarp = (blockIdx.x * 256 + tid) >> 5;
    const int nwarps = gridDim.x * 8;
    const size_t dN = (size_t)depth * N_;
    const unsigned FULL = 0xffffffffu;

    for (int p = gwarp; p < N_ / 4; p += nwarps) {
        const int n0 = 4 * p;

        int ci0 = child_idx[(dN + n0) * K_ + lane];
        int ci1 = child_idx[(dN + n0) * K_ + 32 + lane];

        u64 wfh[4];
#pragma unroll
        for (int q = 0; q < 4; q++) {
            const u64* wq = reinterpret_cast<const u64*>(g_Wx + (dN + n0 + q) * 256);
            wfh[q] = mul2_(__ldg(wq + lane), HALF2);
        }

        u64 hs[4] = {0, 0, 0, 0}, bf[4] = {0, 0, 0, 0};
        u64 acc[12] = {0, 0, 0, 0, 0, 0, 0, 0, 0, 0, 0, 0};

        if (depth != 0) {
            // ---- gather children: branch-free through the zero row ----
#pragma unroll 4
            for (int k = 0; k < K_; k++) {
#pragma unroll
                for (int q = 0; q < 4; q++) {
                    int sl = q * 16 + k;
                    int c = (sl < 32) ? __shfl_sync(FULL, ci0, sl)
                                      : __shfl_sync(FULL, ci1, sl - 32);
                    int off = c * 32 + lane;
                    ulonglong2 hc = __ldg(hcp + off);
                    u64 G2 = __ldg(Gp + off);
                    hs[q] = add2_(hs[q], hc.x);
                    bf[q] = fma2_(hc.y, sig2h(add2_(wfh[q], G2)), bf[q]);
                }
            }

            // ---- iuo = h_sum @ U_iuo via smem broadcast ----
            __syncwarp();
            hb2[lane * 2]     = make_ulonglong2(hs[0], hs[1]);
            hb2[lane * 2 + 1] = make_ulonglong2(hs[2], hs[3]);
            __syncwarp();
#pragma unroll 4
            for (int sl = 0; sl < 32; sl++) {
                ulonglong2 hA = hb2[sl * 2];       // broadcast
                ulonglong2 hB = hb2[sl * 2 + 1];
                float l0, h0, l1, h1, l2, h2, l3, h3;
                upk2(hA.x, l0, h0); upk2(hA.y, l1, h1);
                upk2(hB.x, l2, h2); upk2(hB.y, l3, h3);
                u64 he[4] = {pk2(l0, l0), pk2(l1, l1), pk2(l2, l2), pk2(l3, l3)};
                u64 ho[4] = {pk2(h0, h0), pk2(h1, h1), pk2(h2, h2), pk2(h3, h3)};
                const ulonglong2* Up = reinterpret_cast<const ulonglong2*>(U2 + sl * 192);
#pragma unroll
                for (int m = 0; m < 3; m++) {
                    ulonglong2 uu = Up[m * 32 + lane];
#pragma unroll
                    for (int q = 0; q < 4; q++) {
                        acc[3 * q + m] = fma2_(he[q], uu.x, acc[3 * q + m]);
                        acc[3 * q + m] = fma2_(ho[q], uu.y, acc[3 * q + m]);
                    }
                }
            }
        }

        // ---- gates (packed) ----
        u64 nc[4], nh[4];
#pragma unroll
        for (int q = 0; q < 4; q++) {
            const u64* wq = reinterpret_cast<const u64*>(g_Wx + (dN + n0 + q) * 256);
            u64 ig = sig2h(mul2_(add2_(acc[3 * q],     __ldg(wq + 32 + lane)), HALF2));
            u64 ug = tanh2(add2_(acc[3 * q + 1],       __ldg(wq + 64 + lane)));
            u64 og = sig2h(mul2_(add2_(acc[3 * q + 2], __ldg(wq + 96 + lane)), HALF2));
            nc[q] = fma2_(ig, ug, bf[q]);
            nh[q] = mul2_(og, tanh2(nc[q]));
        }

        if (out) {   // final depth: write result only
            u64* o64 = reinterpret_cast<u64*>(out);
#pragma unroll
            for (int q = 0; q < 4; q++) o64[(size_t)(n0 + q) * 32 + lane] = nh[q];
        } else {
            // ---- G_next = 0.5 * (new_h @ U_f) via smem broadcast ----
            __syncwarp();
            hb2[lane * 2]     = make_ulonglong2(nh[0], nh[1]);
            hb2[lane * 2 + 1] = make_ulonglong2(nh[2], nh[3]);
            __syncwarp();
            u64 g[4] = {0, 0, 0, 0};
            const ulonglong2* Uf22 = reinterpret_cast<const ulonglong2*>(Uf2);
#pragma unroll 4
            for (int sl = 0; sl < 32; sl++) {
                ulonglong2 hA = hb2[sl * 2];
                ulonglong2 hB = hb2[sl * 2 + 1];
                float l0, h0, l1, h1, l2, h2, l3, h3;
                upk2(hA.x, l0, h0); upk2(hA.y, l1, h1);
                upk2(hB.x, l2, h2); upk2(hB.y, l3, h3);
                ulonglong2 uf = Uf22[sl * 32 + lane];
                g[0] = fma2_(pk2(l0, l0), uf.x, g[0]); g[0] = fma2_(pk2(h0, h0), uf.y, g[0]);
                g[1] = fma2_(pk2(l1, l1), uf.x, g[1]); g[1] = fma2_(pk2(h1, h1), uf.y, g[1]);
                g[2] = fma2_(pk2(l2, l2), uf.x, g[2]); g[2] = fma2_(pk2(h2, h2), uf.y, g[2]);
                g[3] = fma2_(pk2(l3, l3), uf.x, g[3]); g[3] = fma2_(pk2(h3, h3), uf.y, g[3]);
            }
#pragma unroll
            for (int q = 0; q < 4; q++) {
                size_t row = (size_t)(n0 + q + 1) * 32 + lane;
                hcn[row] = make_ulonglong2(nh[q], nc[q]);
                Gn[row] = g[q];
            }
        }
    }
}

static const int NODE_SMEM = (6144 + 2048 + 1024) * 8;  // 73,728 B -> 3 CTAs/SM

extern "C" void kernel_launch(void* const* d_in, const int* in_sizes, int n_in,
                              void* d_out, int out_size) {
    const int*   labels    = (const int*)d_in[0];
    const int*   child_idx = (const int*)d_in[1];
    const float* E         = (const float*)d_in[2];
    const float* Ww        = (const float*)d_in[3];
    const float* Wb        = (const float*)d_in[4];
    const float* Uf        = (const float*)d_in[5];
    const float* Uiuo      = (const float*)d_in[6];
    float*       out       = (float*)d_out;

    cudaFuncSetAttribute(node_kernel, cudaFuncAttributeMaxDynamicSharedMemorySize,
                         NODE_SMEM);

    wx_kernel<<<(D_ * N_) / 64, 256>>>(labels, E, Ww, Wb);
    for (int d = 0; d < D_; d++) {
        node_kernel<<<444, 256, NODE_SMEM>>>(child_idx, Uf, Uiuo,
                                             (d == D_ - 1) ? out : nullptr, d);
    }
}

// round 7
// speedup vs baseline: 1.0705x; 1.0705x over previous
#include <cuda_runtime.h>
#include <cuda_bf16.h>
#include <cstdint>

#define D_ 6
#define N_ 32768
#define K_ 16
#define DIN_ 64
#define DOUT_ 64

typedef unsigned long long u64;

// SoA ping-pong state. {h,c} packed per (row, dim-pair) as ulonglong2 (16B),
// G separate u64. Row 0 = zero row for masked children: .bss zero, never written.
__device__ ulonglong2 g_hc[2][(N_ + 1) * 32];
__device__ u64 g_G2[2][(N_ + 1) * 32];   // G = 0.5 * (h @ U_f), pre-halved
// Precomputed Wx for all depths: [6*N][256], cols = [f | i | u | o]
__device__ float g_Wx[(size_t)D_ * N_ * 4 * DOUT_];

#define HALF2 0x3F0000003F000000ULL   // {0.5f, 0.5f}

__device__ __forceinline__ u64 pk2(float lo, float hi) {
    u64 r; asm("mov.b64 %0, {%1,%2};" : "=l"(r) : "f"(lo), "f"(hi)); return r;
}
__device__ __forceinline__ void upk2(u64 v, float& lo, float& hi) {
    asm("mov.b64 {%0,%1}, %2;" : "=f"(lo), "=f"(hi) : "l"(v));
}
__device__ __forceinline__ u64 fma2_(u64 a, u64 b, u64 c) {
    u64 d; asm("fma.rn.f32x2 %0, %1, %2, %3;" : "=l"(d) : "l"(a), "l"(b), "l"(c)); return d;
}
__device__ __forceinline__ u64 add2_(u64 a, u64 b) {
    u64 d; asm("add.rn.f32x2 %0, %1, %2;" : "=l"(d) : "l"(a), "l"(b)); return d;
}
__device__ __forceinline__ u64 mul2_(u64 a, u64 b) {
    u64 d; asm("mul.rn.f32x2 %0, %1, %2;" : "=l"(d) : "l"(a), "l"(b)); return d;
}
__device__ __forceinline__ float tanha(float x) {
    float y; asm("tanh.approx.f32 %0, %1;" : "=f"(y) : "f"(x)); return y;
}
__device__ __forceinline__ u64 sig2h(u64 argHalf) {   // sigmoid(2*arg), arg pre-halved
    float a, b; upk2(argHalf, a, b);
    return fma2_(pk2(tanha(a), tanha(b)), HALF2, HALF2);
}
__device__ __forceinline__ u64 tanh2(u64 v) {
    float a, b; upk2(v, a, b);
    return pk2(tanha(a), tanha(b));
}

__device__ __forceinline__ uint32_t smem_u32(const void* p) {
    uint32_t a;
    asm("{ .reg .u64 t; cvta.to.shared.u64 t, %1; cvt.u32.u64 %0, t; }" : "=r"(a) : "l"(p));
    return a;
}
// bf16x2 pack: low half = lo argument
__device__ __forceinline__ uint32_t bf2pk(float lo, float hi) {
    uint32_t r;
    asm("cvt.rn.bf16x2.f32 %0, %1, %2;" : "=r"(r) : "f"(hi), "f"(lo));
    return r;
}
#define SW128(off) ((off) ^ (((off) >> 3) & 0x70))

__device__ __forceinline__ void ldm_x4(uint32_t* r, uint32_t addr) {
    asm volatile("ldmatrix.sync.aligned.m8n8.x4.shared.b16 {%0,%1,%2,%3}, [%4];"
                 : "=r"(r[0]), "=r"(r[1]), "=r"(r[2]), "=r"(r[3]) : "r"(addr));
}
__device__ __forceinline__ void mma16816(float* c, const uint32_t* a,
                                         uint32_t b0, uint32_t b1) {
    asm volatile(
        "mma.sync.aligned.m16n8k16.row.col.f32.bf16.bf16.f32 "
        "{%0,%1,%2,%3}, {%4,%5,%6,%7}, {%8,%9}, {%0,%1,%2,%3};"
        : "+f"(c[0]), "+f"(c[1]), "+f"(c[2]), "+f"(c[3])
        : "r"(a[0]), "r"(a[1]), "r"(a[2]), "r"(a[3]), "r"(b0), "r"(b1));
}

// ======================= wx GEMM: split-bf16 3-pass mma.sync =======================
// Block = 256 thr (8 warps, 4m x 2n) computing 128 node-rows x 128 cols of
// Wx = E[labels] @ W_w + W_b. Grid = (6N/128) x 2 column halves.
#define WXA_HI 0
#define WXA_LO 16384
#define WXB_HI 32768
#define WXB_LO 49152
#define WX_SMEM 65536

__global__ __launch_bounds__(256) void wx_mma_kernel(const int* __restrict__ labels,
                                                     const float* __restrict__ E,
                                                     const float* __restrict__ Ww,
                                                     const float* __restrict__ Wb) {
    extern __shared__ char smc[];
    __shared__ int lab_s[128];
    uint32_t sb = smem_u32(smc);
    const int t = threadIdx.x;
    const int lane = t & 31, w = t >> 5;
    const int rowbase = (blockIdx.x >> 1) * 128;   // global node row
    const int nb_g = (blockIdx.x & 1) * 128;       // global column base

    if (t < 128) lab_s[t] = labels[rowbase + t];
    __syncthreads();

    // ---- A: gather embeddings -> bf16 hi/lo, SW128 k-major [128 r][64 k] ----
#pragma unroll
    for (int i = 0; i < 8; i++) {
        int linear = i * 256 + t;           // 2048 u64 slots
        int r = linear >> 4, f = linear & 15;
        float4 v = __ldg(reinterpret_cast<const float4*>(
                             E + (size_t)lab_s[r] * DIN_) + f);
        uint32_t h01 = bf2pk(v.x, v.y), h23 = bf2pk(v.z, v.w);
        float l0 = v.x - __uint_as_float(h01 << 16);
        float l1 = v.y - __uint_as_float(h01 & 0xFFFF0000u);
        float l2 = v.z - __uint_as_float(h23 << 16);
        float l3 = v.w - __uint_as_float(h23 & 0xFFFF0000u);
        uint32_t q01 = bf2pk(l0, l1), q23 = bf2pk(l2, l3);
        uint32_t off = SW128((uint32_t)(r * 128 + f * 8));
        *reinterpret_cast<u64*>(smc + WXA_HI + off) = ((u64)h23 << 32) | h01;
        *reinterpret_cast<u64*>(smc + WXA_LO + off) = ((u64)q23 << 32) | q01;
    }
    // ---- B: W_w column-half -> bf16 hi/lo, SW128 [128 n][64 k] ----
#pragma unroll
    for (int i = 0; i < 16; i++) {
        int linear = i * 256 + t;           // 4096 k-pair slots
        int kp = linear >> 7, n = linear & 127;
        float w0 = __ldg(Ww + (2 * kp) * 256 + nb_g + n);
        float w1 = __ldg(Ww + (2 * kp + 1) * 256 + nb_g + n);
        uint32_t hp = bf2pk(w0, w1);
        float l0 = w0 - __uint_as_float(hp << 16);
        float l1 = w1 - __uint_as_float(hp & 0xFFFF0000u);
        uint32_t lp = bf2pk(l0, l1);
        uint32_t off = SW128((uint32_t)(n * 128 + kp * 4));
        *reinterpret_cast<uint32_t*>(smc + WXB_HI + off) = hp;
        *reinterpret_cast<uint32_t*>(smc + WXB_LO + off) = lp;
    }
    __syncthreads();

    // ---- MMA: warp w -> rows 32*(w&3) .. +31, cols 64*(w>>2) .. +63 ----
    const int mbase = 32 * (w & 3);
    const int nbase = 64 * (w >> 2);
    // ldmatrix per-thread row selector: lane 0-7 -> m0, 8-15 -> m1(+8 rows),
    // 16-23 -> m2 (+8 k-bytes... +16B), 24-31 -> m3.
    const int lrow = ((lane >> 3) & 1) * 8 + (lane & 7);
    const int lkb  = (lane >> 4) * 16;

    float acc[2][8][4];
#pragma unroll
    for (int mt = 0; mt < 2; mt++)
#pragma unroll
        for (int nt = 0; nt < 8; nt++)
#pragma unroll
            for (int e = 0; e < 4; e++) acc[mt][nt][e] = 0.f;

#pragma unroll
    for (int pass = 0; pass < 3; pass++) {
        const uint32_t Ab = sb + ((pass == 1) ? WXA_LO : WXA_HI);
        const uint32_t Bb = sb + ((pass == 2) ? WXB_LO : WXB_HI);
#pragma unroll
        for (int kc = 0; kc < 4; kc++) {
            const int koff = kc * 32 + lkb;
            uint32_t a[2][4];
#pragma unroll
            for (int mt = 0; mt < 2; mt++) {
                int r = mbase + 16 * mt + lrow;
                ldm_x4(a[mt], Ab + SW128((uint32_t)(r * 128 + koff)));
            }
#pragma unroll
            for (int tp = 0; tp < 4; tp++) {
                int n = nbase + tp * 16 + lrow;
                uint32_t b[4];
                ldm_x4(b, Bb + SW128((uint32_t)(n * 128 + koff)));
                mma16816(acc[0][2 * tp],     a[0], b[0], b[2]);
                mma16816(acc[0][2 * tp + 1], a[0], b[1], b[3]);
                mma16816(acc[1][2 * tp],     a[1], b[0], b[2]);
                mma16816(acc[1][2 * tp + 1], a[1], b[1], b[3]);
            }
        }
    }

    // ---- epilogue: + bias, f32x2 stores to g_Wx ----
    const int gid = lane >> 2, qc = lane & 3;
#pragma unroll
    for (int mt = 0; mt < 2; mt++) {
#pragma unroll
        for (int nt = 0; nt < 8; nt++) {
            int col = nb_g + nbase + nt * 8 + 2 * qc;
            float2 bia = __ldg(reinterpret_cast<const float2*>(Wb + col));
            int row0 = rowbase + mbase + 16 * mt + gid;
            u64* p0 = reinterpret_cast<u64*>(g_Wx + (size_t)row0 * 256 + col);
            u64* p1 = reinterpret_cast<u64*>(g_Wx + (size_t)(row0 + 8) * 256 + col);
            *p0 = pk2(acc[mt][nt][0] + bia.x, acc[mt][nt][1] + bia.y);
            *p1 = pk2(acc[mt][nt][2] + bia.x, acc[mt][nt][3] + bia.y);
        }
    }
}

// ======================= node kernel (shfl broadcast + vector LDS) =======================
__global__ __launch_bounds__(256, 3) void node_kernel(const int* __restrict__ child_idx,
                                                      const float* __restrict__ Uf,
                                                      const float* __restrict__ Uiuo,
                                                      float* __restrict__ out,
                                                      int depth) {
    const int rb = depth & 1, wb = rb ^ 1;
    const ulonglong2* __restrict__ hcp = g_hc[rb];
    const u64* __restrict__ Gp = g_G2[rb];
    ulonglong2* __restrict__ hcn = g_hc[wb];
    u64* __restrict__ Gn = g_G2[wb];

    extern __shared__ u64 smu[];
    // U2: [32 sl][3 m][32 lane][2 par]; par: d=2sl (x), d=2sl+1 (y)
    u64* U2  = smu;                 // 48KB
    u64* Uf2 = smu + 6144;          // [32 sl][32 lane][2 par], pre-scaled 0.5 -> 16KB

    int tid = threadIdx.x;
    for (int e = tid; e < 6144; e += 256) {
        int par = e & 1, ln = (e >> 1) & 31, m = (e >> 6) % 3, sl = e / 192;
        int d = 2 * sl + par, col = m * 64 + 2 * ln;
        U2[e] = pk2(Uiuo[d * 192 + col], Uiuo[d * 192 + col + 1]);
    }
    for (int e = tid; e < 2048; e += 256) {
        int par = e & 1, ln = (e >> 1) & 31, sl = e >> 6;
        int d = 2 * sl + par;
        Uf2[e] = pk2(0.5f * Uf[d * 64 + 2 * ln], 0.5f * Uf[d * 64 + 2 * ln + 1]);
    }
    __syncthreads();   // only block barrier

    const int lane = tid & 31;
    const int gwarp = (blockIdx.x * 256 + tid) >> 5;
    const int nwarps = gridDim.x * 8;
    const size_t dN = (size_t)depth * N_;
    const unsigned FULL = 0xffffffffu;

    for (int p = gwarp; p < N_ / 4; p += nwarps) {
        const int n0 = 4 * p;

        int ci0 = child_idx[(dN + n0) * K_ + lane];
        int ci1 = child_idx[(dN + n0) * K_ + 32 + lane];

        u64 wfh[4];
#pragma unroll
        for (int q = 0; q < 4; q++) {
            const u64* wq = reinterpret_cast<const u64*>(g_Wx + (dN + n0 + q) * 256);
            wfh[q] = mul2_(__ldg(wq + lane), HALF2);
        }

        u64 hs[4] = {0, 0, 0, 0}, bf[4] = {0, 0, 0, 0};
        u64 acc[12] = {0, 0, 0, 0, 0, 0, 0, 0, 0, 0, 0, 0};

        if (depth != 0) {
            // ---- gather children: branch-free through the zero row ----
#pragma unroll 4
            for (int k = 0; k < K_; k++) {
#pragma unroll
                for (int q = 0; q < 4; q++) {
                    int sl = q * 16 + k;
                    int c = (sl < 32) ? __shfl_sync(FULL, ci0, sl)
                                      : __shfl_sync(FULL, ci1, sl - 32);
                    int off = c * 32 + lane;
                    ulonglong2 hc = __ldg(hcp + off);
                    u64 G2 = __ldg(Gp + off);
                    hs[q] = add2_(hs[q], hc.x);
                    bf[q] = fma2_(hc.y, sig2h(add2_(wfh[q], G2)), bf[q]);
                }
            }

            // ---- iuo = h_sum @ U_iuo: shfl broadcast + LDS.128 U ----
            float hsl[4], hsh[4];
#pragma unroll
            for (int q = 0; q < 4; q++) upk2(hs[q], hsl[q], hsh[q]);
#pragma unroll 4
            for (int sl = 0; sl < 32; sl++) {
                const ulonglong2* Up = reinterpret_cast<const ulonglong2*>(U2 + sl * 192);
                ulonglong2 u0 = Up[lane], u1 = Up[32 + lane], u2 = Up[64 + lane];
#pragma unroll
                for (int q = 0; q < 4; q++) {
                    float he = __shfl_sync(FULL, hsl[q], sl);
                    float ho = __shfl_sync(FULL, hsh[q], sl);
                    u64 he2 = pk2(he, he), ho2 = pk2(ho, ho);
                    acc[3 * q]     = fma2_(he2, u0.x, acc[3 * q]);
                    acc[3 * q + 1] = fma2_(he2, u1.x, acc[3 * q + 1]);
                    acc[3 * q + 2] = fma2_(he2, u2.x, acc[3 * q + 2]);
                    acc[3 * q]     = fma2_(ho2, u0.y, acc[3 * q]);
                    acc[3 * q + 1] = fma2_(ho2, u1.y, acc[3 * q + 1]);
                    acc[3 * q + 2] = fma2_(ho2, u2.y, acc[3 * q + 2]);
                }
            }
        }

        // ---- gates (packed) ----
        u64 nc[4], nh[4];
        float nl[4], nhg[4];
#pragma unroll
        for (int q = 0; q < 4; q++) {
            const u64* wq = reinterpret_cast<const u64*>(g_Wx + (dN + n0 + q) * 256);
            u64 ig = sig2h(mul2_(add2_(acc[3 * q],     __ldg(wq + 32 + lane)), HALF2));
            u64 ug = tanh2(add2_(acc[3 * q + 1],       __ldg(wq + 64 + lane)));
            u64 og = sig2h(mul2_(add2_(acc[3 * q + 2], __ldg(wq + 96 + lane)), HALF2));
            nc[q] = fma2_(ig, ug, bf[q]);
            nh[q] = mul2_(og, tanh2(nc[q]));
            upk2(nh[q], nl[q], nhg[q]);
        }

        if (out) {   // final depth
            u64* o64 = reinterpret_cast<u64*>(out);
#pragma unroll
            for (int q = 0; q < 4; q++) o64[(size_t)(n0 + q) * 32 + lane] = nh[q];
        } else {
            // ---- G_next = 0.5 * (new_h @ U_f) ----
            u64 g[4] = {0, 0, 0, 0};
            const ulonglong2* Uf22 = reinterpret_cast<const ulonglong2*>(Uf2);
#pragma unroll 4
            for (int sl = 0; sl < 32; sl++) {
                ulonglong2 uf = Uf22[sl * 32 + lane];
#pragma unroll
                for (int q = 0; q < 4; q++) {
                    float he = __shfl_sync(FULL, nl[q], sl);
                    float ho = __shfl_sync(FULL, nhg[q], sl);
                    g[q] = fma2_(pk2(he, he), uf.x, g[q]);
                    g[q] = fma2_(pk2(ho, ho), uf.y, g[q]);
                }
            }
#pragma unroll
            for (int q = 0; q < 4; q++) {
                size_t row = (size_t)(n0 + q + 1) * 32 + lane;
                hcn[row] = make_ulonglong2(nh[q], nc[q]);
                Gn[row] = g[q];
            }
        }
    }
}

static const int NODE_SMEM = (6144 + 2048) * 8;  // 65,536 B -> 3 CTAs/SM

extern "C" void kernel_launch(void* const* d_in, const int* in_sizes, int n_in,
                              void* d_out, int out_size) {
    const int*   labels    = (const int*)d_in[0];
    const int*   child_idx = (const int*)d_in[1];
    const float* E         = (const float*)d_in[2];
    const float* Ww        = (const float*)d_in[3];
    const float* Wb        = (const float*)d_in[4];
    const float* Uf        = (const float*)d_in[5];
    const float* Uiuo      = (const float*)d_in[6];
    float*       out       = (float*)d_out;

    cudaFuncSetAttribute(node_kernel, cudaFuncAttributeMaxDynamicSharedMemorySize,
                         NODE_SMEM);
    cudaFuncSetAttribute(wx_mma_kernel, cudaFuncAttributeMaxDynamicSharedMemorySize,
                         WX_SMEM);

    wx_mma_kernel<<<(D_ * N_) / 128 * 2, 256, WX_SMEM>>>(labels, E, Ww, Wb);
    for (int d = 0; d < D_; d++) {
        node_kernel<<<444, 256, NODE_SMEM>>>(child_idx, Uf, Uiuo,
                                             (d == D_ - 1) ? out : nullptr, d);
    }
}

// round 8
// speedup vs baseline: 1.2209x; 1.1405x over previous
#include <cuda_runtime.h>
#include <cuda_bf16.h>
#include <cstdint>

#define D_ 6
#define N_ 32768
#define K_ 16
#define DIN_ 64
#define DOUT_ 64

typedef unsigned long long u64;

// SoA ping-pong state. {h,c} packed per (row, dim-pair) as ulonglong2 (16B),
// G separate u64. Row 0 = zero row for masked children: .bss zero, never written.
__device__ ulonglong2 g_hc[2][(N_ + 1) * 32];
__device__ u64 g_G2[2][(N_ + 1) * 32];   // G = 0.5 * (h @ U_f), pre-halved
// Precomputed Wx for all depths: [6*N][256], cols = [f | i | u | o]
__device__ float g_Wx[(size_t)D_ * N_ * 4 * DOUT_];
// Pre-swizzled split-bf16 weight planes (smem image): UAhi|UAlo|UFhi|UFlo
__device__ uint32_t g_Wpl[16384];

#define HALF2 0x3F0000003F000000ULL   // {0.5f, 0.5f}

__device__ __forceinline__ u64 pk2(float lo, float hi) {
    u64 r; asm("mov.b64 %0, {%1,%2};" : "=l"(r) : "f"(lo), "f"(hi)); return r;
}
__device__ __forceinline__ void upk2(u64 v, float& lo, float& hi) {
    asm("mov.b64 {%0,%1}, %2;" : "=f"(lo), "=f"(hi) : "l"(v));
}
__device__ __forceinline__ u64 fma2_(u64 a, u64 b, u64 c) {
    u64 d; asm("fma.rn.f32x2 %0, %1, %2, %3;" : "=l"(d) : "l"(a), "l"(b), "l"(c)); return d;
}
__device__ __forceinline__ u64 add2_(u64 a, u64 b) {
    u64 d; asm("add.rn.f32x2 %0, %1, %2;" : "=l"(d) : "l"(a), "l"(b)); return d;
}
__device__ __forceinline__ u64 mul2_(u64 a, u64 b) {
    u64 d; asm("mul.rn.f32x2 %0, %1, %2;" : "=l"(d) : "l"(a), "l"(b)); return d;
}
__device__ __forceinline__ float tanha(float x) {
    float y; asm("tanh.approx.f32 %0, %1;" : "=f"(y) : "f"(x)); return y;
}
__device__ __forceinline__ u64 sig2h(u64 argHalf) {   // sigmoid(2*arg), arg pre-halved
    float a, b; upk2(argHalf, a, b);
    return fma2_(pk2(tanha(a), tanha(b)), HALF2, HALF2);
}
__device__ __forceinline__ u64 tanh2(u64 v) {
    float a, b; upk2(v, a, b);
    return pk2(tanha(a), tanha(b));
}
__device__ __forceinline__ uint32_t smem_u32(const void* p) {
    uint32_t a;
    asm("{ .reg .u64 t; cvta.to.shared.u64 t, %1; cvt.u32.u64 %0, t; }" : "=r"(a) : "l"(p));
    return a;
}
// bf16x2 pack: low half = first arg
__device__ __forceinline__ uint32_t bf2pk(float lo, float hi) {
    uint32_t r;
    asm("cvt.rn.bf16x2.f32 %0, %1, %2;" : "=r"(r) : "f"(hi), "f"(lo));
    return r;
}
#define SW128(off) ((off) ^ (((off) >> 3) & 0x70))

__device__ __forceinline__ void ldm_x4(uint32_t* r, uint32_t addr) {
    asm volatile("ldmatrix.sync.aligned.m8n8.x4.shared.b16 {%0,%1,%2,%3}, [%4];"
                 : "=r"(r[0]), "=r"(r[1]), "=r"(r[2]), "=r"(r[3]) : "r"(addr));
}
__device__ __forceinline__ void mma16816(float* c, const uint32_t* a,
                                         uint32_t b0, uint32_t b1) {
    asm volatile(
        "mma.sync.aligned.m16n8k16.row.col.f32.bf16.bf16.f32 "
        "{%0,%1,%2,%3}, {%4,%5,%6,%7}, {%8,%9}, {%0,%1,%2,%3};"
        : "+f"(c[0]), "+f"(c[1]), "+f"(c[2]), "+f"(c[3])
        : "r"(a[0]), "r"(a[1]), "r"(a[2]), "r"(a[3]), "r"(b0), "r"(b1));
}

// ============ prep: U_iuo/U_f -> swizzled split-bf16 planes in global ============
// Layout (u32 words): [0,6144) UA_HI [192n][32kp]; [6144,12288) UA_LO;
//                     [12288,14336) UF_HI [64n][32kp] (x0.5); [14336,16384) UF_LO.
__global__ void prep_kernel(const float* __restrict__ Uf,
                            const float* __restrict__ Uiuo) {
    int idx0 = blockIdx.x * 256 + threadIdx.x;
    for (int idx = idx0; idx < 8192; idx += 2048) {
        if (idx < 6144) {
            int n = idx >> 5, kp = idx & 31;
            float x = Uiuo[(2 * kp) * 192 + n], y = Uiuo[(2 * kp + 1) * 192 + n];
            uint32_t hi = bf2pk(x, y);
            float rl = x - __uint_as_float(hi << 16);
            float rr = y - __uint_as_float(hi & 0xFFFF0000u);
            uint32_t lo = bf2pk(rl, rr);
            uint32_t off = SW128((uint32_t)(n * 128 + kp * 4)) >> 2;
            g_Wpl[off] = hi;
            g_Wpl[6144 + off] = lo;
        } else {
            int i = idx - 6144;
            int n = i >> 5, kp = i & 31;
            float x = 0.5f * Uf[(2 * kp) * 64 + n], y = 0.5f * Uf[(2 * kp + 1) * 64 + n];
            uint32_t hi = bf2pk(x, y);
            float rl = x - __uint_as_float(hi << 16);
            float rr = y - __uint_as_float(hi & 0xFFFF0000u);
            uint32_t lo = bf2pk(rl, rr);
            uint32_t off = SW128((uint32_t)(n * 128 + kp * 4)) >> 2;
            g_Wpl[12288 + off] = hi;
            g_Wpl[14336 + off] = lo;
        }
    }
}

// ======================= wx GEMM: split-bf16 3-pass mma.sync (validated) ==========
#define WXA_HI 0
#define WXA_LO 16384
#define WXB_HI 32768
#define WXB_LO 49152
#define WX_SMEM 65536

__global__ __launch_bounds__(256) void wx_mma_kernel(const int* __restrict__ labels,
                                                     const float* __restrict__ E,
                                                     const float* __restrict__ Ww,
                                                     const float* __restrict__ Wb) {
    extern __shared__ char smc[];
    __shared__ int lab_s[128];
    uint32_t sb = smem_u32(smc);
    const int t = threadIdx.x;
    const int lane = t & 31, w = t >> 5;
    const int rowbase = (blockIdx.x >> 1) * 128;
    const int nb_g = (blockIdx.x & 1) * 128;

    if (t < 128) lab_s[t] = labels[rowbase + t];
    __syncthreads();

#pragma unroll
    for (int i = 0; i < 8; i++) {
        int linear = i * 256 + t;
        int r = linear >> 4, f = linear & 15;
        float4 v = __ldg(reinterpret_cast<const float4*>(
                             E + (size_t)lab_s[r] * DIN_) + f);
        uint32_t h01 = bf2pk(v.x, v.y), h23 = bf2pk(v.z, v.w);
        float l0 = v.x - __uint_as_float(h01 << 16);
        float l1 = v.y - __uint_as_float(h01 & 0xFFFF0000u);
        float l2 = v.z - __uint_as_float(h23 << 16);
        float l3 = v.w - __uint_as_float(h23 & 0xFFFF0000u);
        uint32_t q01 = bf2pk(l0, l1), q23 = bf2pk(l2, l3);
        uint32_t off = SW128((uint32_t)(r * 128 + f * 8));
        *reinterpret_cast<u64*>(smc + WXA_HI + off) = ((u64)h23 << 32) | h01;
        *reinterpret_cast<u64*>(smc + WXA_LO + off) = ((u64)q23 << 32) | q01;
    }
#pragma unroll
    for (int i = 0; i < 16; i++) {
        int linear = i * 256 + t;
        int kp = linear >> 7, n = linear & 127;
        float w0 = __ldg(Ww + (2 * kp) * 256 + nb_g + n);
        float w1 = __ldg(Ww + (2 * kp + 1) * 256 + nb_g + n);
        uint32_t hp = bf2pk(w0, w1);
        float l0 = w0 - __uint_as_float(hp << 16);
        float l1 = w1 - __uint_as_float(hp & 0xFFFF0000u);
        uint32_t lp = bf2pk(l0, l1);
        uint32_t off = SW128((uint32_t)(n * 128 + kp * 4));
        *reinterpret_cast<uint32_t*>(smc + WXB_HI + off) = hp;
        *reinterpret_cast<uint32_t*>(smc + WXB_LO + off) = lp;
    }
    __syncthreads();

    const int mbase = 32 * (w & 3);
    const int nbase = 64 * (w >> 2);
    const int lrow = ((lane >> 3) & 1) * 8 + (lane & 7);
    const int lkb  = (lane >> 4) * 16;

    float acc[2][8][4];
#pragma unroll
    for (int mt = 0; mt < 2; mt++)
#pragma unroll
        for (int nt = 0; nt < 8; nt++)
#pragma unroll
            for (int e = 0; e < 4; e++) acc[mt][nt][e] = 0.f;

#pragma unroll
    for (int pass = 0; pass < 3; pass++) {
        const uint32_t Ab = sb + ((pass == 1) ? WXA_LO : WXA_HI);
        const uint32_t Bb = sb + ((pass == 2) ? WXB_LO : WXB_HI);
#pragma unroll
        for (int kc = 0; kc < 4; kc++) {
            const int koff = kc * 32 + lkb;
            uint32_t a[2][4];
#pragma unroll
            for (int mt = 0; mt < 2; mt++) {
                int r = mbase + 16 * mt + lrow;
                ldm_x4(a[mt], Ab + SW128((uint32_t)(r * 128 + koff)));
            }
#pragma unroll
            for (int tp = 0; tp < 4; tp++) {
                int n = nbase + tp * 16 + lrow;
                uint32_t b[4];
                ldm_x4(b, Bb + SW128((uint32_t)(n * 128 + koff)));
                mma16816(acc[0][2 * tp],     a[0], b[0], b[2]);
                mma16816(acc[0][2 * tp + 1], a[0], b[1], b[3]);
                mma16816(acc[1][2 * tp],     a[1], b[0], b[2]);
                mma16816(acc[1][2 * tp + 1], a[1], b[1], b[3]);
            }
        }
    }

    const int gid = lane >> 2, qc = lane & 3;
#pragma unroll
    for (int mt = 0; mt < 2; mt++) {
#pragma unroll
        for (int nt = 0; nt < 8; nt++) {
            int col = nb_g + nbase + nt * 8 + 2 * qc;
            float2 bia = __ldg(reinterpret_cast<const float2*>(Wb + col));
            int row0 = rowbase + mbase + 16 * mt + gid;
            u64* p0 = reinterpret_cast<u64*>(g_Wx + (size_t)row0 * 256 + col);
            u64* p1 = reinterpret_cast<u64*>(g_Wx + (size_t)(row0 + 8) * 256 + col);
            *p0 = pk2(acc[mt][nt][0] + bia.x, acc[mt][nt][1] + bia.y);
            *p1 = pk2(acc[mt][nt][2] + bia.x, acc[mt][nt][3] + bia.y);
        }
    }
}

// ======================= node kernel: gather + tensor-core matvecs =======================
// smem byte offsets
#define UA_HI 0
#define UA_LO 24576
#define UF_HI 49152
#define UF_LO 57344
#define AS_HI 65536
#define AS_LO 73728
#define BFOF  81920
#define NODE_SMEM 98816   // BF = 64 rows x 33 u64 (padded)

__global__ __launch_bounds__(256, 2) void node_kernel(const int* __restrict__ child_idx,
                                                      float* __restrict__ out,
                                                      int depth) {
    extern __shared__ char smc[];
    const uint32_t sb = smem_u32(smc);
    const int tid = threadIdx.x, lane = tid & 31, w = tid >> 5;

    // stage pre-built weight planes (64KB straight copy)
    for (int i = tid; i < 4096; i += 256)
        reinterpret_cast<uint4*>(smc)[i] = __ldg(reinterpret_cast<const uint4*>(g_Wpl) + i);
    __syncthreads();

    const int rb = depth & 1, wb = rb ^ 1;
    const ulonglong2* __restrict__ hcp = g_hc[rb];
    const u64* __restrict__ Gp = g_G2[rb];
    ulonglong2* __restrict__ hcn = g_hc[wb];
    u64* __restrict__ Gn = g_G2[wb];
    const size_t dN = (size_t)depth * N_;
    const int nb = blockIdx.x * 64;
    const unsigned FULL = 0xffffffffu;
    u64* BF64 = reinterpret_cast<u64*>(smc + BFOF);

    // ================= phase 1: gather (8 warps x 4 nodes x 2 iters) =================
    if (depth != 0) {
#pragma unroll
        for (int iter = 0; iter < 2; iter++) {
            const int n0 = nb + 32 * iter + 4 * w;
            int ci0 = child_idx[(dN + n0) * K_ + lane];
            int ci1 = child_idx[(dN + n0) * K_ + 32 + lane];
            u64 wfh[4], hs[4] = {0, 0, 0, 0}, bfa[4] = {0, 0, 0, 0};
#pragma unroll
            for (int q4 = 0; q4 < 4; q4++)
                wfh[q4] = mul2_(__ldg(reinterpret_cast<const u64*>(
                                          g_Wx + (dN + n0 + q4) * 256) + lane), HALF2);
#pragma unroll 4
            for (int k = 0; k < K_; k++) {
#pragma unroll
                for (int q4 = 0; q4 < 4; q4++) {
                    int sl = q4 * 16 + k;
                    int c = (sl < 32) ? __shfl_sync(FULL, ci0, sl)
                                      : __shfl_sync(FULL, ci1, sl - 32);
                    int off = c * 32 + lane;
                    ulonglong2 hc = __ldg(hcp + off);
                    u64 G2 = __ldg(Gp + off);
                    hs[q4] = add2_(hs[q4], hc.x);
                    bfa[q4] = fma2_(hc.y, sig2h(add2_(wfh[q4], G2)), bfa[q4]);
                }
            }
#pragma unroll
            for (int q4 = 0; q4 < 4; q4++) {
                int r = 32 * iter + 4 * w + q4;
                float xl, xh; upk2(hs[q4], xl, xh);
                uint32_t hi = bf2pk(xl, xh);
                float rl = xl - __uint_as_float(hi << 16);
                float rr = xh - __uint_as_float(hi & 0xFFFF0000u);
                uint32_t lo = bf2pk(rl, rr);
                uint32_t o = SW128((uint32_t)(r * 128 + 4 * lane));
                *reinterpret_cast<uint32_t*>(smc + AS_HI + o) = hi;
                *reinterpret_cast<uint32_t*>(smc + AS_LO + o) = lo;
                BF64[r * 33 + lane] = bfa[q4];
            }
        }
        __syncthreads();
    }

    // ================= phase 2: iuo = hs @ U_iuo (3-pass split-bf16 mma) ============
    const int g = lane >> 2, q = lane & 3;
    const int mrow = 16 * (w & 3), cg = w >> 2;
    const int lrow = ((lane >> 3) & 1) * 8 + (lane & 7);
    const int lkb  = (lane >> 4) * 16;

    float acc[3][4][4];
#pragma unroll
    for (int b = 0; b < 3; b++)
#pragma unroll
        for (int j4 = 0; j4 < 4; j4++)
#pragma unroll
            for (int e = 0; e < 4; e++) acc[b][j4][e] = 0.f;

    if (depth != 0) {
#pragma unroll
        for (int pass = 0; pass < 3; pass++) {
            const uint32_t Ab = sb + ((pass == 1) ? AS_LO : AS_HI);
            const uint32_t Bb = sb + ((pass == 2) ? UA_LO : UA_HI);
#pragma unroll
            for (int kc = 0; kc < 4; kc++) {
                const int koff = kc * 32 + lkb;
                uint32_t a[4];
                ldm_x4(a, Ab + SW128((uint32_t)((mrow + lrow) * 128 + koff)));
#pragma unroll
                for (int b = 0; b < 3; b++)
#pragma unroll
                    for (int tp = 0; tp < 2; tp++) {
                        int nrow = b * 64 + cg * 32 + tp * 16 + lrow;
                        uint32_t bb[4];
                        ldm_x4(bb, Bb + SW128((uint32_t)(nrow * 128 + koff)));
                        mma16816(acc[b][2 * tp],     a, bb[0], bb[2]);
                        mma16816(acc[b][2 * tp + 1], a, bb[1], bb[3]);
                    }
            }
        }
    }

    // ================= phase 3: gates in fragment registers ==========================
    u64 nhv[4][2];
#pragma unroll
    for (int j4 = 0; j4 < 4; j4++) {
        const int dp = 16 * cg + 4 * j4 + q;
#pragma unroll
        for (int rh = 0; rh < 2; rh++) {
            const int r = mrow + 8 * rh + g;
            const u64* wq = reinterpret_cast<const u64*>(g_Wx + (dN + nb + r) * 256);
            u64 ai = pk2(acc[0][j4][2 * rh], acc[0][j4][2 * rh + 1]);
            u64 au = pk2(acc[1][j4][2 * rh], acc[1][j4][2 * rh + 1]);
            u64 ao = pk2(acc[2][j4][2 * rh], acc[2][j4][2 * rh + 1]);
            u64 ig = sig2h(mul2_(add2_(ai, __ldg(wq + 32 + dp)), HALF2));
            u64 ug = tanh2(add2_(au, __ldg(wq + 64 + dp)));
            u64 og = sig2h(mul2_(add2_(ao, __ldg(wq + 96 + dp)), HALF2));
            u64 bfv = (depth != 0) ? BF64[r * 33 + dp] : 0ULL;
            u64 ncv = fma2_(ig, ug, bfv);
            u64 nh = mul2_(og, tanh2(ncv));
            nhv[j4][rh] = nh;
            if (out) {
                reinterpret_cast<u64*>(out)[(size_t)(nb + r) * 32 + dp] = nh;
            } else {
                hcn[(size_t)(nb + r + 1) * 32 + dp] = make_ulonglong2(nh, ncv);
            }
        }
    }
    if (out) return;   // final depth: no next-state projection

    // ================= phase 4: stage new_h, G = 0.5*(new_h @ U_f) ===================
    __syncthreads();   // all warps done reading AS (hs)
#pragma unroll
    for (int j4 = 0; j4 < 4; j4++) {
        const int dp = 16 * cg + 4 * j4 + q;
#pragma unroll
        for (int rh = 0; rh < 2; rh++) {
            const int r = mrow + 8 * rh + g;
            float xl, xh; upk2(nhv[j4][rh], xl, xh);
            uint32_t hi = bf2pk(xl, xh);
            float rl = xl - __uint_as_float(hi << 16);
            float rr = xh - __uint_as_float(hi & 0xFFFF0000u);
            uint32_t lo = bf2pk(rl, rr);
            uint32_t o = SW128((uint32_t)(r * 128 + 4 * dp));
            *reinterpret_cast<uint32_t*>(smc + AS_HI + o) = hi;
            *reinterpret_cast<uint32_t*>(smc + AS_LO + o) = lo;
        }
    }
    __syncthreads();

    float ga[4][4];
#pragma unroll
    for (int t = 0; t < 4; t++)
#pragma unroll
        for (int e = 0; e < 4; e++) ga[t][e] = 0.f;

#pragma unroll
    for (int pass = 0; pass < 3; pass++) {
        const uint32_t Ab = sb + ((pass == 1) ? AS_LO : AS_HI);
        const uint32_t Bb = sb + ((pass == 2) ? UF_LO : UF_HI);
#pragma unroll
        for (int kc = 0; kc < 4; kc++) {
            const int koff = kc * 32 + lkb;
            uint32_t a[4];
            ldm_x4(a, Ab + SW128((uint32_t)((mrow + lrow) * 128 + koff)));
#pragma unroll
            for (int tp = 0; tp < 2; tp++) {
                int nrow = cg * 32 + tp * 16 + lrow;
                uint32_t bb[4];
                ldm_x4(bb, Bb + SW128((uint32_t)(nrow * 128 + koff)));
                mma16816(ga[2 * tp],     a, bb[0], bb[2]);
                mma16816(ga[2 * tp + 1], a, bb[1], bb[3]);
            }
        }
    }
#pragma unroll
    for (int tg = 0; tg < 4; tg++) {
        const int dp = 16 * cg + 4 * tg + q;
#pragma unroll
        for (int rh = 0; rh < 2; rh++) {
            const int r = mrow + 8 * rh + g;
            Gn[(size_t)(nb + r + 1) * 32 + dp] = pk2(ga[tg][2 * rh], ga[tg][2 * rh + 1]);
        }
    }
}

extern "C" void kernel_launch(void* const* d_in, const int* in_sizes, int n_in,
                              void* d_out, int out_size) {
    const int*   labels    = (const int*)d_in[0];
    const int*   child_idx = (const int*)d_in[1];
    const float* E         = (const float*)d_in[2];
    const float* Ww        = (const float*)d_in[3];
    const float* Wb        = (const float*)d_in[4];
    const float* Uf        = (const float*)d_in[5];
    const float* Uiuo      = (const float*)d_in[6];
    float*       out       = (float*)d_out;

    cudaFuncSetAttribute(node_kernel, cudaFuncAttributeMaxDynamicSharedMemorySize,
                         NODE_SMEM);
    cudaFuncSetAttribute(wx_mma_kernel, cudaFuncAttributeMaxDynamicSharedMemorySize,
                         WX_SMEM);

    prep_kernel<<<8, 256>>>(Uf, Uiuo);
    wx_mma_kernel<<<(D_ * N_) / 128 * 2, 256, WX_SMEM>>>(labels, E, Ww, Wb);
    for (int d = 0; d < D_; d++) {
        node_kernel<<<N_ / 64, 256, NODE_SMEM>>>(child_idx,
                                                 (d == D_ - 1) ? out : nullptr, d);
    }
}

// round 9
// speedup vs baseline: 1.3217x; 1.0826x over previous
#include <cuda_runtime.h>
#include <cuda_bf16.h>
#include <cuda_fp16.h>
#include <cstdint>

#define D_ 6
#define N_ 32768
#define K_ 16
#define DIN_ 64
#define DOUT_ 64

typedef unsigned long long u64;

// SoA ping-pong state per (row, dim-pair):
//   g_c2:  c as f32x2 (u64)
//   g_hG:  low u32 = h as f16x2, high u32 = G(=0.5*h@Uf) as f16x2
// Row 0 = zero row for masked children: .bss zero, never written.
__device__ u64 g_c2[2][(N_ + 1) * 32];
__device__ u64 g_hG[2][(N_ + 1) * 32];
// Precomputed Wx for all depths: [6*N][256], cols = [f | i | u | o]
__device__ float g_Wx[(size_t)D_ * N_ * 4 * DOUT_];
// Pre-swizzled split-bf16 weight planes (smem image): UAhi|UAlo|UFhi|UFlo
__device__ uint32_t g_Wpl[16384];

#define HALF2 0x3F0000003F000000ULL   // {0.5f, 0.5f}

__device__ __forceinline__ u64 pk2(float lo, float hi) {
    u64 r; asm("mov.b64 %0, {%1,%2};" : "=l"(r) : "f"(lo), "f"(hi)); return r;
}
__device__ __forceinline__ void upk2(u64 v, float& lo, float& hi) {
    asm("mov.b64 {%0,%1}, %2;" : "=f"(lo), "=f"(hi) : "l"(v));
}
__device__ __forceinline__ u64 fma2_(u64 a, u64 b, u64 c) {
    u64 d; asm("fma.rn.f32x2 %0, %1, %2, %3;" : "=l"(d) : "l"(a), "l"(b), "l"(c)); return d;
}
__device__ __forceinline__ u64 add2_(u64 a, u64 b) {
    u64 d; asm("add.rn.f32x2 %0, %1, %2;" : "=l"(d) : "l"(a), "l"(b)); return d;
}
__device__ __forceinline__ u64 mul2_(u64 a, u64 b) {
    u64 d; asm("mul.rn.f32x2 %0, %1, %2;" : "=l"(d) : "l"(a), "l"(b)); return d;
}
__device__ __forceinline__ float tanha(float x) {
    float y; asm("tanh.approx.f32 %0, %1;" : "=f"(y) : "f"(x)); return y;
}
__device__ __forceinline__ u64 sig2h(u64 argHalf) {   // sigmoid(2*arg), arg pre-halved
    float a, b; upk2(argHalf, a, b);
    return fma2_(pk2(tanha(a), tanha(b)), HALF2, HALF2);
}
__device__ __forceinline__ u64 tanh2(u64 v) {
    float a, b; upk2(v, a, b);
    return pk2(tanha(a), tanha(b));
}
__device__ __forceinline__ uint32_t smem_u32(const void* p) {
    uint32_t a;
    asm("{ .reg .u64 t; cvta.to.shared.u64 t, %1; cvt.u32.u64 %0, t; }" : "=r"(a) : "l"(p));
    return a;
}
// bf16x2 pack: low half = first arg
__device__ __forceinline__ uint32_t bf2pk(float lo, float hi) {
    uint32_t r;
    asm("cvt.rn.bf16x2.f32 %0, %1, %2;" : "=r"(r) : "f"(hi), "f"(lo));
    return r;
}
// f16x2 <-> f32 pair
__device__ __forceinline__ uint32_t h2pk(float lo, float hi) {
    __half2 h = __float22half2_rn(make_float2(lo, hi));
    return *reinterpret_cast<uint32_t*>(&h);
}
__device__ __forceinline__ u64 h2up(uint32_t v) {   // f16x2 -> f32x2 (u64)
    __half2 h = *reinterpret_cast<__half2*>(&v);
    float2 f = __half22float2(h);
    return pk2(f.x, f.y);
}
#define SW128(off) ((off) ^ (((off) >> 3) & 0x70))

__device__ __forceinline__ void ldm_x4(uint32_t* r, uint32_t addr) {
    asm volatile("ldmatrix.sync.aligned.m8n8.x4.shared.b16 {%0,%1,%2,%3}, [%4];"
                 : "=r"(r[0]), "=r"(r[1]), "=r"(r[2]), "=r"(r[3]) : "r"(addr));
}
__device__ __forceinline__ void mma16816(float* c, const uint32_t* a,
                                         uint32_t b0, uint32_t b1) {
    asm volatile(
        "mma.sync.aligned.m16n8k16.row.col.f32.bf16.bf16.f32 "
        "{%0,%1,%2,%3}, {%4,%5,%6,%7}, {%8,%9}, {%0,%1,%2,%3};"
        : "+f"(c[0]), "+f"(c[1]), "+f"(c[2]), "+f"(c[3])
        : "r"(a[0]), "r"(a[1]), "r"(a[2]), "r"(a[3]), "r"(b0), "r"(b1));
}

// ============ prep: U_iuo/U_f -> swizzled split-bf16 planes in global ============
__global__ void prep_kernel(const float* __restrict__ Uf,
                            const float* __restrict__ Uiuo) {
    int idx0 = blockIdx.x * 256 + threadIdx.x;
    for (int idx = idx0; idx < 8192; idx += 2048) {
        if (idx < 6144) {
            int n = idx >> 5, kp = idx & 31;
            float x = Uiuo[(2 * kp) * 192 + n], y = Uiuo[(2 * kp + 1) * 192 + n];
            uint32_t hi = bf2pk(x, y);
            float rl = x - __uint_as_float(hi << 16);
            float rr = y - __uint_as_float(hi & 0xFFFF0000u);
            uint32_t lo = bf2pk(rl, rr);
            uint32_t off = SW128((uint32_t)(n * 128 + kp * 4)) >> 2;
            g_Wpl[off] = hi;
            g_Wpl[6144 + off] = lo;
        } else {
            int i = idx - 6144;
            int n = i >> 5, kp = i & 31;
            float x = 0.5f * Uf[(2 * kp) * 64 + n], y = 0.5f * Uf[(2 * kp + 1) * 64 + n];
            uint32_t hi = bf2pk(x, y);
            float rl = x - __uint_as_float(hi << 16);
            float rr = y - __uint_as_float(hi & 0xFFFF0000u);
            uint32_t lo = bf2pk(rl, rr);
            uint32_t off = SW128((uint32_t)(n * 128 + kp * 4)) >> 2;
            g_Wpl[12288 + off] = hi;
            g_Wpl[14336 + off] = lo;
        }
    }
}

// ======================= wx GEMM: split-bf16 3-pass mma.sync (validated) ==========
#define WXA_HI 0
#define WXA_LO 16384
#define WXB_HI 32768
#define WXB_LO 49152
#define WX_SMEM 65536

__global__ __launch_bounds__(256) void wx_mma_kernel(const int* __restrict__ labels,
                                                     const float* __restrict__ E,
                                                     const float* __restrict__ Ww,
                                                     const float* __restrict__ Wb) {
    extern __shared__ char smc[];
    __shared__ int lab_s[128];
    uint32_t sb = smem_u32(smc);
    const int t = threadIdx.x;
    const int lane = t & 31, w = t >> 5;
    const int rowbase = (blockIdx.x >> 1) * 128;
    const int nb_g = (blockIdx.x & 1) * 128;

    if (t < 128) lab_s[t] = labels[rowbase + t];
    __syncthreads();

#pragma unroll
    for (int i = 0; i < 8; i++) {
        int linear = i * 256 + t;
        int r = linear >> 4, f = linear & 15;
        float4 v = __ldg(reinterpret_cast<const float4*>(
                             E + (size_t)lab_s[r] * DIN_) + f);
        uint32_t h01 = bf2pk(v.x, v.y), h23 = bf2pk(v.z, v.w);
        float l0 = v.x - __uint_as_float(h01 << 16);
        float l1 = v.y - __uint_as_float(h01 & 0xFFFF0000u);
        float l2 = v.z - __uint_as_float(h23 << 16);
        float l3 = v.w - __uint_as_float(h23 & 0xFFFF0000u);
        uint32_t q01 = bf2pk(l0, l1), q23 = bf2pk(l2, l3);
        uint32_t off = SW128((uint32_t)(r * 128 + f * 8));
        *reinterpret_cast<u64*>(smc + WXA_HI + off) = ((u64)h23 << 32) | h01;
        *reinterpret_cast<u64*>(smc + WXA_LO + off) = ((u64)q23 << 32) | q01;
    }
#pragma unroll
    for (int i = 0; i < 16; i++) {
        int linear = i * 256 + t;
        int kp = linear >> 7, n = linear & 127;
        float w0 = __ldg(Ww + (2 * kp) * 256 + nb_g + n);
        float w1 = __ldg(Ww + (2 * kp + 1) * 256 + nb_g + n);
        uint32_t hp = bf2pk(w0, w1);
        float l0 = w0 - __uint_as_float(hp << 16);
        float l1 = w1 - __uint_as_float(hp & 0xFFFF0000u);
        uint32_t lp = bf2pk(l0, l1);
        uint32_t off = SW128((uint32_t)(n * 128 + kp * 4));
        *reinterpret_cast<uint32_t*>(smc + WXB_HI + off) = hp;
        *reinterpret_cast<uint32_t*>(smc + WXB_LO + off) = lp;
    }
    __syncthreads();

    const int mbase = 32 * (w & 3);
    const int nbase = 64 * (w >> 2);
    const int lrow = ((lane >> 3) & 1) * 8 + (lane & 7);
    const int lkb  = (lane >> 4) * 16;

    float acc[2][8][4];
#pragma unroll
    for (int mt = 0; mt < 2; mt++)
#pragma unroll
        for (int nt = 0; nt < 8; nt++)
#pragma unroll
            for (int e = 0; e < 4; e++) acc[mt][nt][e] = 0.f;

#pragma unroll
    for (int pass = 0; pass < 3; pass++) {
        const uint32_t Ab = sb + ((pass == 1) ? WXA_LO : WXA_HI);
        const uint32_t Bb = sb + ((pass == 2) ? WXB_LO : WXB_HI);
#pragma unroll
        for (int kc = 0; kc < 4; kc++) {
            const int koff = kc * 32 + lkb;
            uint32_t a[2][4];
#pragma unroll
            for (int mt = 0; mt < 2; mt++) {
                int r = mbase + 16 * mt + lrow;
                ldm_x4(a[mt], Ab + SW128((uint32_t)(r * 128 + koff)));
            }
#pragma unroll
            for (int tp = 0; tp < 4; tp++) {
                int n = nbase + tp * 16 + lrow;
                uint32_t b[4];
                ldm_x4(b, Bb + SW128((uint32_t)(n * 128 + koff)));
                mma16816(acc[0][2 * tp],     a[0], b[0], b[2]);
                mma16816(acc[0][2 * tp + 1], a[0], b[1], b[3]);
                mma16816(acc[1][2 * tp],     a[1], b[0], b[2]);
                mma16816(acc[1][2 * tp + 1], a[1], b[1], b[3]);
            }
        }
    }

    const int gid = lane >> 2, qc = lane & 3;
#pragma unroll
    for (int mt = 0; mt < 2; mt++) {
#pragma unroll
        for (int nt = 0; nt < 8; nt++) {
            int col = nb_g + nbase + nt * 8 + 2 * qc;
            float2 bia = __ldg(reinterpret_cast<const float2*>(Wb + col));
            int row0 = rowbase + mbase + 16 * mt + gid;
            u64* p0 = reinterpret_cast<u64*>(g_Wx + (size_t)row0 * 256 + col);
            u64* p1 = reinterpret_cast<u64*>(g_Wx + (size_t)(row0 + 8) * 256 + col);
            *p0 = pk2(acc[mt][nt][0] + bia.x, acc[mt][nt][1] + bia.y);
            *p1 = pk2(acc[mt][nt][2] + bia.x, acc[mt][nt][3] + bia.y);
        }
    }
}

// ======================= node kernel: persistent, fp16 h/G state ==================
#define UA_HI 0
#define UA_LO 24576
#define UF_HI 49152
#define UF_LO 57344
#define AS_HI 65536
#define AS_LO 73728
#define BFOF  81920
#define NODE_SMEM 98816   // BF = 64 rows x 33 u64 (padded)

__global__ __launch_bounds__(256, 2) void node_kernel(const int* __restrict__ child_idx,
                                                      float* __restrict__ out,
                                                      int depth) {
    extern __shared__ char smc[];
    const uint32_t sb = smem_u32(smc);
    const int tid = threadIdx.x, lane = tid & 31, w = tid >> 5;

    // stage pre-built weight planes ONCE per CTA (covers both tiles)
    for (int i = tid; i < 4096; i += 256)
        reinterpret_cast<uint4*>(smc)[i] = __ldg(reinterpret_cast<const uint4*>(g_Wpl) + i);
    __syncthreads();

    const int rb = depth & 1, wb = rb ^ 1;
    const u64* __restrict__ cp  = g_c2[rb];
    const u64* __restrict__ hgp = g_hG[rb];
    u64* __restrict__ cn  = g_c2[wb];
    u64* __restrict__ hgn = g_hG[wb];
    const size_t dN = (size_t)depth * N_;
    const unsigned FULL = 0xffffffffu;
    u64* BF64 = reinterpret_cast<u64*>(smc + BFOF);

    const int g = lane >> 2, q = lane & 3;
    const int mrow = 16 * (w & 3), cg = w >> 2;
    const int lrow = ((lane >> 3) & 1) * 8 + (lane & 7);
    const int lkb  = (lane >> 4) * 16;

    for (int ti = 0; ti < 2; ti++) {
        const int nb = (blockIdx.x * 2 + ti) * 64;

        // ================= phase 1: gather =================
        if (depth != 0) {
#pragma unroll
            for (int iter = 0; iter < 2; iter++) {
                const int n0 = nb + 32 * iter + 4 * w;
                int ci0 = child_idx[(dN + n0) * K_ + lane];
                int ci1 = child_idx[(dN + n0) * K_ + 32 + lane];
                u64 wfh[4], hs[4] = {0, 0, 0, 0}, bfa[4] = {0, 0, 0, 0};
#pragma unroll
                for (int q4 = 0; q4 < 4; q4++)
                    wfh[q4] = mul2_(__ldg(reinterpret_cast<const u64*>(
                                              g_Wx + (dN + n0 + q4) * 256) + lane), HALF2);
#pragma unroll 4
                for (int k = 0; k < K_; k++) {
#pragma unroll
                    for (int q4 = 0; q4 < 4; q4++) {
                        int sl = q4 * 16 + k;
                        int c = (sl < 32) ? __shfl_sync(FULL, ci0, sl)
                                          : __shfl_sync(FULL, ci1, sl - 32);
                        int off = c * 32 + lane;
                        u64 cv = __ldg(cp + off);
                        u64 hg = __ldg(hgp + off);
                        hs[q4] = add2_(hs[q4], h2up((uint32_t)hg));
                        bfa[q4] = fma2_(cv, sig2h(add2_(wfh[q4],
                                                        h2up((uint32_t)(hg >> 32)))),
                                        bfa[q4]);
                    }
                }
#pragma unroll
                for (int q4 = 0; q4 < 4; q4++) {
                    int r = 32 * iter + 4 * w + q4;
                    float xl, xh; upk2(hs[q4], xl, xh);
                    uint32_t hi = bf2pk(xl, xh);
                    float rl = xl - __uint_as_float(hi << 16);
                    float rr = xh - __uint_as_float(hi & 0xFFFF0000u);
                    uint32_t lo = bf2pk(rl, rr);
                    uint32_t o = SW128((uint32_t)(r * 128 + 4 * lane));
                    *reinterpret_cast<uint32_t*>(smc + AS_HI + o) = hi;
                    *reinterpret_cast<uint32_t*>(smc + AS_LO + o) = lo;
                    BF64[r * 33 + lane] = bfa[q4];
                }
            }
            __syncthreads();
        }

        // ================= phase 2: iuo = hs @ U_iuo =================
        float acc[3][4][4];
#pragma unroll
        for (int b = 0; b < 3; b++)
#pragma unroll
            for (int j4 = 0; j4 < 4; j4++)
#pragma unroll
                for (int e = 0; e < 4; e++) acc[b][j4][e] = 0.f;

        if (depth != 0) {
#pragma unroll
            for (int pass = 0; pass < 3; pass++) {
                const uint32_t Ab = sb + ((pass == 1) ? AS_LO : AS_HI);
                const uint32_t Bb = sb + ((pass == 2) ? UA_LO : UA_HI);
#pragma unroll
                for (int kc = 0; kc < 4; kc++) {
                    const int koff = kc * 32 + lkb;
                    uint32_t a[4];
                    ldm_x4(a, Ab + SW128((uint32_t)((mrow + lrow) * 128 + koff)));
#pragma unroll
                    for (int b = 0; b < 3; b++)
#pragma unroll
                        for (int tp = 0; tp < 2; tp++) {
                            int nrow = b * 64 + cg * 32 + tp * 16 + lrow;
                            uint32_t bb[4];
                            ldm_x4(bb, Bb + SW128((uint32_t)(nrow * 128 + koff)));
                            mma16816(acc[b][2 * tp],     a, bb[0], bb[2]);
                            mma16816(acc[b][2 * tp + 1], a, bb[1], bb[3]);
                        }
                }
            }
        }

        // ================= phase 3: gates =================
        u64 nhv[4][2];
#pragma unroll
        for (int j4 = 0; j4 < 4; j4++) {
            const int dp = 16 * cg + 4 * j4 + q;
#pragma unroll
            for (int rh = 0; rh < 2; rh++) {
                const int r = mrow + 8 * rh + g;
                const u64* wq = reinterpret_cast<const u64*>(g_Wx + (dN + nb + r) * 256);
                u64 ai = pk2(acc[0][j4][2 * rh], acc[0][j4][2 * rh + 1]);
                u64 au = pk2(acc[1][j4][2 * rh], acc[1][j4][2 * rh + 1]);
                u64 ao = pk2(acc[2][j4][2 * rh], acc[2][j4][2 * rh + 1]);
                u64 ig = sig2h(mul2_(add2_(ai, __ldg(wq + 32 + dp)), HALF2));
                u64 ug = tanh2(add2_(au, __ldg(wq + 64 + dp)));
                u64 og = sig2h(mul2_(add2_(ao, __ldg(wq + 96 + dp)), HALF2));
                u64 bfv = (depth != 0) ? BF64[r * 33 + dp] : 0ULL;
                u64 ncv = fma2_(ig, ug, bfv);
                u64 nh = mul2_(og, tanh2(ncv));
                nhv[j4][rh] = nh;
                if (out) {
                    reinterpret_cast<u64*>(out)[(size_t)(nb + r) * 32 + dp] = nh;
                } else {
                    cn[(size_t)(nb + r + 1) * 32 + dp] = ncv;
                }
            }
        }

        if (!out) {
            // ============ phase 4: stage new_h, G = 0.5*(new_h @ U_f) ============
            __syncthreads();   // all warps done reading AS
#pragma unroll
            for (int j4 = 0; j4 < 4; j4++) {
                const int dp = 16 * cg + 4 * j4 + q;
#pragma unroll
                for (int rh = 0; rh < 2; rh++) {
                    const int r = mrow + 8 * rh + g;
                    float xl, xh; upk2(nhv[j4][rh], xl, xh);
                    uint32_t hi = bf2pk(xl, xh);
                    float rl = xl - __uint_as_float(hi << 16);
                    float rr = xh - __uint_as_float(hi & 0xFFFF0000u);
                    uint32_t lo = bf2pk(rl, rr);
                    uint32_t o = SW128((uint32_t)(r * 128 + 4 * dp));
                    *reinterpret_cast<uint32_t*>(smc + AS_HI + o) = hi;
                    *reinterpret_cast<uint32_t*>(smc + AS_LO + o) = lo;
                }
            }
            __syncthreads();

            float ga[4][4];
#pragma unroll
            for (int t = 0; t < 4; t++)
#pragma unroll
                for (int e = 0; e < 4; e++) ga[t][e] = 0.f;

#pragma unroll
            for (int pass = 0; pass < 3; pass++) {
                const uint32_t Ab = sb + ((pass == 1) ? AS_LO : AS_HI);
                const uint32_t Bb = sb + ((pass == 2) ? UF_LO : UF_HI);
#pragma unroll
                for (int kc = 0; kc < 4; kc++) {
                    const int koff = kc * 32 + lkb;
                    uint32_t a[4];
                    ldm_x4(a, Ab + SW128((uint32_t)((mrow + lrow) * 128 + koff)));
#pragma unroll
                    for (int tp = 0; tp < 2; tp++) {
                        int nrow = cg * 32 + tp * 16 + lrow;
                        uint32_t bb[4];
                        ldm_x4(bb, Bb + SW128((uint32_t)(nrow * 128 + koff)));
                        mma16816(ga[2 * tp],     a, bb[0], bb[2]);
                        mma16816(ga[2 * tp + 1], a, bb[1], bb[3]);
                    }
                }
            }
#pragma unroll
            for (int tg = 0; tg < 4; tg++) {
                const int dp = 16 * cg + 4 * tg + q;
#pragma unroll
                for (int rh = 0; rh < 2; rh++) {
                    const int r = mrow + 8 * rh + g;
                    float xl, xh; upk2(nhv[tg][rh], xl, xh);
                    uint32_t hu = h2pk(xl, xh);
                    uint32_t gu = h2pk(ga[tg][2 * rh], ga[tg][2 * rh + 1]);
                    hgn[(size_t)(nb + r + 1) * 32 + dp] = ((u64)gu << 32) | hu;
                }
            }
        }
        if (ti == 0) __syncthreads();   // AS/BF reuse hazard across tiles
    }
}

extern "C" void kernel_launch(void* const* d_in, const int* in_sizes, int n_in,
                              void* d_out, int out_size) {
    const int*   labels    = (const int*)d_in[0];
    const int*   child_idx = (const int*)d_in[1];
    const float* E         = (const float*)d_in[2];
    const float* Ww        = (const float*)d_in[3];
    const float* Wb        = (const float*)d_in[4];
    const float* Uf        = (const float*)d_in[5];
    const float* Uiuo      = (const float*)d_in[6];
    float*       out       = (float*)d_out;

    cudaFuncSetAttribute(node_kernel, cudaFuncAttributeMaxDynamicSharedMemorySize,
                         NODE_SMEM);
    cudaFuncSetAttribute(wx_mma_kernel, cudaFuncAttributeMaxDynamicSharedMemorySize,
                         WX_SMEM);

    prep_kernel<<<8, 256>>>(Uf, Uiuo);
    wx_mma_kernel<<<(D_ * N_) / 128 * 2, 256, WX_SMEM>>>(labels, E, Ww, Wb);
    for (int d = 0; d < D_; d++) {
        node_kernel<<<N_ / 128, 256, NODE_SMEM>>>(child_idx,
                                                  (d == D_ - 1) ? out : nullptr, d);
    }
}

// round 10
// speedup vs baseline: 1.3533x; 1.0240x over previous
#include <cuda_runtime.h>
#include <cuda_bf16.h>
#include <cuda_fp16.h>
#include <cstdint>

#define D_ 6
#define N_ 32768
#define K_ 16
#define DIN_ 64
#define DOUT_ 64

typedef unsigned long long u64;

// Interleaved ping-pong state, 16B per (row, dim-pair):
//   word0 (u64): c as f32x2
//   word1 (u64): low u32 = h as f16x2, high u32 = G(=0.5*h@Uf) as f16x2
// Row 0 = zero row for masked children: .bss zero, never written.
__device__ u64 g_st[2][(N_ + 1) * 64];
// Precomputed Wx for all depths: [6*N][256], cols = [f | i | u | o]
__device__ float g_Wx[(size_t)D_ * N_ * 4 * DOUT_];
// Pre-swizzled split-bf16 weight planes (smem image): UAhi|UAlo|UFhi|UFlo
__device__ uint32_t g_Wpl[16384];
// software grid barrier
__device__ unsigned g_cnt;
__device__ unsigned g_gen;

#define HALF2 0x3F0000003F000000ULL   // {0.5f, 0.5f}

__device__ __forceinline__ u64 pk2(float lo, float hi) {
    u64 r; asm("mov.b64 %0, {%1,%2};" : "=l"(r) : "f"(lo), "f"(hi)); return r;
}
__device__ __forceinline__ void upk2(u64 v, float& lo, float& hi) {
    asm("mov.b64 {%0,%1}, %2;" : "=f"(lo), "=f"(hi) : "l"(v));
}
__device__ __forceinline__ u64 fma2_(u64 a, u64 b, u64 c) {
    u64 d; asm("fma.rn.f32x2 %0, %1, %2, %3;" : "=l"(d) : "l"(a), "l"(b), "l"(c)); return d;
}
__device__ __forceinline__ u64 add2_(u64 a, u64 b) {
    u64 d; asm("add.rn.f32x2 %0, %1, %2;" : "=l"(d) : "l"(a), "l"(b)); return d;
}
__device__ __forceinline__ u64 mul2_(u64 a, u64 b) {
    u64 d; asm("mul.rn.f32x2 %0, %1, %2;" : "=l"(d) : "l"(a), "l"(b)); return d;
}
__device__ __forceinline__ float tanha(float x) {
    float y; asm("tanh.approx.f32 %0, %1;" : "=f"(y) : "f"(x)); return y;
}
__device__ __forceinline__ u64 sig2h(u64 argHalf) {   // sigmoid(2*arg), arg pre-halved
    float a, b; upk2(argHalf, a, b);
    return fma2_(pk2(tanha(a), tanha(b)), HALF2, HALF2);
}
__device__ __forceinline__ u64 tanh2(u64 v) {
    float a, b; upk2(v, a, b);
    return pk2(tanha(a), tanha(b));
}
__device__ __forceinline__ uint32_t smem_u32(const void* p) {
    uint32_t a;
    asm("{ .reg .u64 t; cvta.to.shared.u64 t, %1; cvt.u32.u64 %0, t; }" : "=r"(a) : "l"(p));
    return a;
}
__device__ __forceinline__ uint32_t bf2pk(float lo, float hi) {
    uint32_t r;
    asm("cvt.rn.bf16x2.f32 %0, %1, %2;" : "=r"(r) : "f"(hi), "f"(lo));
    return r;
}
__device__ __forceinline__ uint32_t h2pk(float lo, float hi) {
    __half2 h = __float22half2_rn(make_float2(lo, hi));
    return *reinterpret_cast<uint32_t*>(&h);
}
__device__ __forceinline__ u64 h2up(uint32_t v) {   // f16x2 -> f32x2 (u64)
    __half2 h = *reinterpret_cast<__half2*>(&v);
    float2 f = __half22float2(h);
    return pk2(f.x, f.y);
}
#define SW128(off) ((off) ^ (((off) >> 3) & 0x70))

__device__ __forceinline__ void ldm_x4(uint32_t* r, uint32_t addr) {
    asm volatile("ldmatrix.sync.aligned.m8n8.x4.shared.b16 {%0,%1,%2,%3}, [%4];"
                 : "=r"(r[0]), "=r"(r[1]), "=r"(r[2]), "=r"(r[3]) : "r"(addr));
}
__device__ __forceinline__ void mma16816(float* c, const uint32_t* a,
                                         uint32_t b0, uint32_t b1) {
    asm volatile(
        "mma.sync.aligned.m16n8k16.row.col.f32.bf16.bf16.f32 "
        "{%0,%1,%2,%3}, {%4,%5,%6,%7}, {%8,%9}, {%0,%1,%2,%3};"
        : "+f"(c[0]), "+f"(c[1]), "+f"(c[2]), "+f"(c[3])
        : "r"(a[0]), "r"(a[1]), "r"(a[2]), "r"(a[3]), "r"(b0), "r"(b1));
}

// ============ prep: U_iuo/U_f -> swizzled split-bf16 planes in global ============
__global__ void prep_kernel(const float* __restrict__ Uf,
                            const float* __restrict__ Uiuo) {
    int idx0 = blockIdx.x * 256 + threadIdx.x;
    for (int idx = idx0; idx < 8192; idx += 2048) {
        if (idx < 6144) {
            int n = idx >> 5, kp = idx & 31;
            float x = Uiuo[(2 * kp) * 192 + n], y = Uiuo[(2 * kp + 1) * 192 + n];
            uint32_t hi = bf2pk(x, y);
            float rl = x - __uint_as_float(hi << 16);
            float rr = y - __uint_as_float(hi & 0xFFFF0000u);
            uint32_t lo = bf2pk(rl, rr);
            uint32_t off = SW128((uint32_t)(n * 128 + kp * 4)) >> 2;
            g_Wpl[off] = hi;
            g_Wpl[6144 + off] = lo;
        } else {
            int i = idx - 6144;
            int n = i >> 5, kp = i & 31;
            float x = 0.5f * Uf[(2 * kp) * 64 + n], y = 0.5f * Uf[(2 * kp + 1) * 64 + n];
            uint32_t hi = bf2pk(x, y);
            float rl = x - __uint_as_float(hi << 16);
            float rr = y - __uint_as_float(hi & 0xFFFF0000u);
            uint32_t lo = bf2pk(rl, rr);
            uint32_t off = SW128((uint32_t)(n * 128 + kp * 4)) >> 2;
            g_Wpl[12288 + off] = hi;
            g_Wpl[14336 + off] = lo;
        }
    }
}

// ======================= wx GEMM: split-bf16 3-pass mma.sync (validated) ==========
#define WXA_HI 0
#define WXA_LO 16384
#define WXB_HI 32768
#define WXB_LO 49152
#define WX_SMEM 65536

__global__ __launch_bounds__(256) void wx_mma_kernel(const int* __restrict__ labels,
                                                     const float* __restrict__ E,
                                                     const float* __restrict__ Ww,
                                                     const float* __restrict__ Wb) {
    extern __shared__ char smc[];
    __shared__ int lab_s[128];
    uint32_t sb = smem_u32(smc);
    const int t = threadIdx.x;
    const int lane = t & 31, w = t >> 5;
    const int rowbase = (blockIdx.x >> 1) * 128;
    const int nb_g = (blockIdx.x & 1) * 128;

    if (t < 128) lab_s[t] = labels[rowbase + t];
    __syncthreads();

#pragma unroll
    for (int i = 0; i < 8; i++) {
        int linear = i * 256 + t;
        int r = linear >> 4, f = linear & 15;
        float4 v = __ldg(reinterpret_cast<const float4*>(
                             E + (size_t)lab_s[r] * DIN_) + f);
        uint32_t h01 = bf2pk(v.x, v.y), h23 = bf2pk(v.z, v.w);
        float l0 = v.x - __uint_as_float(h01 << 16);
        float l1 = v.y - __uint_as_float(h01 & 0xFFFF0000u);
        float l2 = v.z - __uint_as_float(h23 << 16);
        float l3 = v.w - __uint_as_float(h23 & 0xFFFF0000u);
        uint32_t q01 = bf2pk(l0, l1), q23 = bf2pk(l2, l3);
        uint32_t off = SW128((uint32_t)(r * 128 + f * 8));
        *reinterpret_cast<u64*>(smc + WXA_HI + off) = ((u64)h23 << 32) | h01;
        *reinterpret_cast<u64*>(smc + WXA_LO + off) = ((u64)q23 << 32) | q01;
    }
#pragma unroll
    for (int i = 0; i < 16; i++) {
        int linear = i * 256 + t;
        int kp = linear >> 7, n = linear & 127;
        float w0 = __ldg(Ww + (2 * kp) * 256 + nb_g + n);
        float w1 = __ldg(Ww + (2 * kp + 1) * 256 + nb_g + n);
        uint32_t hp = bf2pk(w0, w1);
        float l0 = w0 - __uint_as_float(hp << 16);
        float l1 = w1 - __uint_as_float(hp & 0xFFFF0000u);
        uint32_t lp = bf2pk(l0, l1);
        uint32_t off = SW128((uint32_t)(n * 128 + kp * 4));
        *reinterpret_cast<uint32_t*>(smc + WXB_HI + off) = hp;
        *reinterpret_cast<uint32_t*>(smc + WXB_LO + off) = lp;
    }
    __syncthreads();

    const int mbase = 32 * (w & 3);
    const int nbase = 64 * (w >> 2);
    const int lrow = ((lane >> 3) & 1) * 8 + (lane & 7);
    const int lkb  = (lane >> 4) * 16;

    float acc[2][8][4];
#pragma unroll
    for (int mt = 0; mt < 2; mt++)
#pragma unroll
        for (int nt = 0; nt < 8; nt++)
#pragma unroll
            for (int e = 0; e < 4; e++) acc[mt][nt][e] = 0.f;

#pragma unroll
    for (int pass = 0; pass < 3; pass++) {
        const uint32_t Ab = sb + ((pass == 1) ? WXA_LO : WXA_HI);
        const uint32_t Bb = sb + ((pass == 2) ? WXB_LO : WXB_HI);
#pragma unroll
        for (int kc = 0; kc < 4; kc++) {
            const int koff = kc * 32 + lkb;
            uint32_t a[2][4];
#pragma unroll
            for (int mt = 0; mt < 2; mt++) {
                int r = mbase + 16 * mt + lrow;
                ldm_x4(a[mt], Ab + SW128((uint32_t)(r * 128 + koff)));
            }
#pragma unroll
            for (int tp = 0; tp < 4; tp++) {
                int n = nbase + tp * 16 + lrow;
                uint32_t b[4];
                ldm_x4(b, Bb + SW128((uint32_t)(n * 128 + koff)));
                mma16816(acc[0][2 * tp],     a[0], b[0], b[2]);
                mma16816(acc[0][2 * tp + 1], a[0], b[1], b[3]);
                mma16816(acc[1][2 * tp],     a[1], b[0], b[2]);
                mma16816(acc[1][2 * tp + 1], a[1], b[1], b[3]);
            }
        }
    }

    const int gid = lane >> 2, qc = lane & 3;
#pragma unroll
    for (int mt = 0; mt < 2; mt++) {
#pragma unroll
        for (int nt = 0; nt < 8; nt++) {
            int col = nb_g + nbase + nt * 8 + 2 * qc;
            float2 bia = __ldg(reinterpret_cast<const float2*>(Wb + col));
            int row0 = rowbase + mbase + 16 * mt + gid;
            u64* p0 = reinterpret_cast<u64*>(g_Wx + (size_t)row0 * 256 + col);
            u64* p1 = reinterpret_cast<u64*>(g_Wx + (size_t)(row0 + 8) * 256 + col);
            *p0 = pk2(acc[mt][nt][0] + bia.x, acc[mt][nt][1] + bia.y);
            *p1 = pk2(acc[mt][nt][2] + bia.x, acc[mt][nt][3] + bia.y);
        }
    }
}

// ========== fused node kernel: persistent over all 6 depths, LDG.128 gather ======
#define UA_HI 0
#define UA_LO 24576
#define UF_HI 49152
#define UF_LO 57344
#define AS_HI 65536
#define AS_LO 73728
#define BFOF  81920
#define NODE_SMEM 98816   // BF = 64 rows x 33 u64 (padded)
#define NODE_GRID 256

__global__ __launch_bounds__(256, 2) void node_all_kernel(const int* __restrict__ child_idx,
                                                          float* __restrict__ out) {
    extern __shared__ char smc[];
    const uint32_t sb = smem_u32(smc);
    const int tid = threadIdx.x, lane = tid & 31, w = tid >> 5;

    // generation snapshot BEFORE first barrier arrival (safe: gen can't advance
    // until this CTA arrives)
    const unsigned gen0 = *((volatile unsigned*)&g_gen);

    // stage pre-built weight planes ONCE per CTA (persists across all depths)
    for (int i = tid; i < 4096; i += 256)
        reinterpret_cast<uint4*>(smc)[i] = __ldg(reinterpret_cast<const uint4*>(g_Wpl) + i);
    __syncthreads();

    u64* BF64 = reinterpret_cast<u64*>(smc + BFOF);
    const unsigned FULL = 0xffffffffu;
    const int g = lane >> 2, q = lane & 3;
    const int mrow = 16 * (w & 3), cg = w >> 2;
    const int lrow = ((lane >> 3) & 1) * 8 + (lane & 7);
    const int lkb  = (lane >> 4) * 16;

    for (int depth = 0; depth < D_; depth++) {
        const int rb = depth & 1;
        const u64* __restrict__ sp = g_st[rb];
        u64* __restrict__ sn = g_st[rb ^ 1];
        const size_t dN = (size_t)depth * N_;
        const bool last = (depth == D_ - 1);

        for (int ti = 0; ti < 2; ti++) {
            const int nb = (blockIdx.x * 2 + ti) * 64;

            // ================= phase 1: gather (LDG.128 per child) =================
            if (depth != 0) {
#pragma unroll
                for (int iter = 0; iter < 2; iter++) {
                    const int n0 = nb + 32 * iter + 4 * w;
                    int ci0 = child_idx[(dN + n0) * K_ + lane];
                    int ci1 = child_idx[(dN + n0) * K_ + 32 + lane];
                    u64 wfh[4], hs[4] = {0, 0, 0, 0}, bfa[4] = {0, 0, 0, 0};
#pragma unroll
                    for (int q4 = 0; q4 < 4; q4++)
                        wfh[q4] = mul2_(__ldg(reinterpret_cast<const u64*>(
                                                  g_Wx + (dN + n0 + q4) * 256) + lane),
                                        HALF2);
#pragma unroll 4
                    for (int k = 0; k < K_; k++) {
#pragma unroll
                        for (int q4 = 0; q4 < 4; q4++) {
                            int sl = q4 * 16 + k;
                            int c = (sl < 32) ? __shfl_sync(FULL, ci0, sl)
                                              : __shfl_sync(FULL, ci1, sl - 32);
                            ulonglong2 s = __ldg(reinterpret_cast<const ulonglong2*>(
                                                     sp + 2 * (c * 32 + lane)));
                            hs[q4] = add2_(hs[q4], h2up((uint32_t)s.y));
                            bfa[q4] = fma2_(s.x,
                                            sig2h(add2_(wfh[q4],
                                                        h2up((uint32_t)(s.y >> 32)))),
                                            bfa[q4]);
                        }
                    }
#pragma unroll
                    for (int q4 = 0; q4 < 4; q4++) {
                        int r = 32 * iter + 4 * w + q4;
                        float xl, xh; upk2(hs[q4], xl, xh);
                        uint32_t hi = bf2pk(xl, xh);
                        float rl = xl - __uint_as_float(hi << 16);
                        float rr = xh - __uint_as_float(hi & 0xFFFF0000u);
                        uint32_t lo = bf2pk(rl, rr);
                        uint32_t o = SW128((uint32_t)(r * 128 + 4 * lane));
                        *reinterpret_cast<uint32_t*>(smc + AS_HI + o) = hi;
                        *reinterpret_cast<uint32_t*>(smc + AS_LO + o) = lo;
                        BF64[r * 33 + lane] = bfa[q4];
                    }
                }
                __syncthreads();
            }

            // ================= phase 2: iuo = hs @ U_iuo =================
            float acc[3][4][4];
#pragma unroll
            for (int b = 0; b < 3; b++)
#pragma unroll
                for (int j4 = 0; j4 < 4; j4++)
#pragma unroll
                    for (int e = 0; e < 4; e++) acc[b][j4][e] = 0.f;

            if (depth != 0) {
#pragma unroll
                for (int pass = 0; pass < 3; pass++) {
                    const uint32_t Ab = sb + ((pass == 1) ? AS_LO : AS_HI);
                    const uint32_t Bb = sb + ((pass == 2) ? UA_LO : UA_HI);
#pragma unroll
                    for (int kc = 0; kc < 4; kc++) {
                        const int koff = kc * 32 + lkb;
                        uint32_t a[4];
                        ldm_x4(a, Ab + SW128((uint32_t)((mrow + lrow) * 128 + koff)));
#pragma unroll
                        for (int b = 0; b < 3; b++)
#pragma unroll
                            for (int tp = 0; tp < 2; tp++) {
                                int nrow = b * 64 + cg * 32 + tp * 16 + lrow;
                                uint32_t bb[4];
                                ldm_x4(bb, Bb + SW128((uint32_t)(nrow * 128 + koff)));
                                mma16816(acc[b][2 * tp],     a, bb[0], bb[2]);
                                mma16816(acc[b][2 * tp + 1], a, bb[1], bb[3]);
                            }
                    }
                }
            }

            // ================= phase 3: gates =================
            u64 nhv[4][2];
#pragma unroll
            for (int j4 = 0; j4 < 4; j4++) {
                const int dp = 16 * cg + 4 * j4 + q;
#pragma unroll
                for (int rh = 0; rh < 2; rh++) {
                    const int r = mrow + 8 * rh + g;
                    const u64* wq = reinterpret_cast<const u64*>(
                                        g_Wx + (dN + nb + r) * 256);
                    u64 ai = pk2(acc[0][j4][2 * rh], acc[0][j4][2 * rh + 1]);
                    u64 au = pk2(acc[1][j4][2 * rh], acc[1][j4][2 * rh + 1]);
                    u64 ao = pk2(acc[2][j4][2 * rh], acc[2][j4][2 * rh + 1]);
                    u64 ig = sig2h(mul2_(add2_(ai, __ldg(wq + 32 + dp)), HALF2));
                    u64 ug = tanh2(add2_(au, __ldg(wq + 64 + dp)));
                    u64 og = sig2h(mul2_(add2_(ao, __ldg(wq + 96 + dp)), HALF2));
                    u64 bfv = (depth != 0) ? BF64[r * 33 + dp] : 0ULL;
                    u64 ncv = fma2_(ig, ug, bfv);
                    u64 nh = mul2_(og, tanh2(ncv));
                    nhv[j4][rh] = nh;
                    if (last) {
                        reinterpret_cast<u64*>(out)[(size_t)(nb + r) * 32 + dp] = nh;
                    } else {
                        sn[2 * ((size_t)(nb + r + 1) * 32 + dp)] = ncv;   // c word
                    }
                }
            }

            if (!last) {
                // ============ phase 4: stage new_h, G = 0.5*(new_h @ U_f) ============
                __syncthreads();   // all warps done reading AS
#pragma unroll
                for (int j4 = 0; j4 < 4; j4++) {
                    const int dp = 16 * cg + 4 * j4 + q;
#pragma unroll
                    for (int rh = 0; rh < 2; rh++) {
                        const int r = mrow + 8 * rh + g;
                        float xl, xh; upk2(nhv[j4][rh], xl, xh);
                        uint32_t hi = bf2pk(xl, xh);
                        float rl = xl - __uint_as_float(hi << 16);
                        float rr = xh - __uint_as_float(hi & 0xFFFF0000u);
                        uint32_t lo = bf2pk(rl, rr);
                        uint32_t o = SW128((uint32_t)(r * 128 + 4 * dp));
                        *reinterpret_cast<uint32_t*>(smc + AS_HI + o) = hi;
                        *reinterpret_cast<uint32_t*>(smc + AS_LO + o) = lo;
                    }
                }
                __syncthreads();

                float ga[4][4];
#pragma unroll
                for (int t2 = 0; t2 < 4; t2++)
#pragma unroll
                    for (int e = 0; e < 4; e++) ga[t2][e] = 0.f;

#pragma unroll
                for (int pass = 0; pass < 3; pass++) {
                    const uint32_t Ab = sb + ((pass == 1) ? AS_LO : AS_HI);
                    const uint32_t Bb = sb + ((pass == 2) ? UF_LO : UF_HI);
#pragma unroll
                    for (int kc = 0; kc < 4; kc++) {
                        const int koff = kc * 32 + lkb;
                        uint32_t a[4];
                        ldm_x4(a, Ab + SW128((uint32_t)((mrow + lrow) * 128 + koff)));
#pragma unroll
                        for (int tp = 0; tp < 2; tp++) {
                            int nrow = cg * 32 + tp * 16 + lrow;
                            uint32_t bb[4];
                            ldm_x4(bb, Bb + SW128((uint32_t)(nrow * 128 + koff)));
                            mma16816(ga[2 * tp],     a, bb[0], bb[2]);
                            mma16816(ga[2 * tp + 1], a, bb[1], bb[3]);
                        }
                    }
                }
#pragma unroll
                for (int tg = 0; tg < 4; tg++) {
                    const int dp = 16 * cg + 4 * tg + q;
#pragma unroll
                    for (int rh = 0; rh < 2; rh++) {
                        const int r = mrow + 8 * rh + g;
                        float xl, xh; upk2(nhv[tg][rh], xl, xh);
                        uint32_t hu = h2pk(xl, xh);
                        uint32_t gu = h2pk(ga[tg][2 * rh], ga[tg][2 * rh + 1]);
                        sn[2 * ((size_t)(nb + r + 1) * 32 + dp) + 1] =
                            ((u64)gu << 32) | hu;                       // hG word
                    }
                }
            }
            if (ti == 0) __syncthreads();   // AS/BF reuse hazard across tiles
        }

        // ================= grid barrier between depths =================
        if (!last) {
            __syncthreads();
            if (tid == 0) {
                __threadfence();
                unsigned a = atomicAdd(&g_cnt, 1u);
                unsigned target = gen0 + (unsigned)depth + 1u;
                if ((a % NODE_GRID) == NODE_GRID - 1) {
                    atomicAdd(&g_gen, 1u);
                } else {
                    while (*((volatile unsigned*)&g_gen) < target) {}
                }
                __threadfence();
            }
            __syncthreads();
        }
    }
}

extern "C" void kernel_launch(void* const* d_in, const int* in_sizes, int n_in,
                              void* d_out, int out_size) {
    const int*   labels    = (const int*)d_in[0];
    const int*   child_idx = (const int*)d_in[1];
    const float* E         = (const float*)d_in[2];
    const float* Ww        = (const float*)d_in[3];
    const float* Wb        = (const float*)d_in[4];
    const float* Uf        = (const float*)d_in[5];
    const float* Uiuo      = (const float*)d_in[6];
    float*       out       = (float*)d_out;

    cudaFuncSetAttribute(node_all_kernel, cudaFuncAttributeMaxDynamicSharedMemorySize,
                         NODE_SMEM);
    cudaFuncSetAttribute(wx_mma_kernel, cudaFuncAttributeMaxDynamicSharedMemorySize,
                         WX_SMEM);

    prep_kernel<<<8, 256>>>(Uf, Uiuo);
    wx_mma_kernel<<<(D_ * N_) / 128 * 2, 256, WX_SMEM>>>(labels, E, Ww, Wb);
    node_all_kernel<<<NODE_GRID, 256, NODE_SMEM>>>(child_idx, out);
}

// round 11
// speedup vs baseline: 1.4193x; 1.0487x over previous
#include <cuda_runtime.h>
#include <cuda_bf16.h>
#include <cuda_fp16.h>
#include <cstdint>

#define D_ 6
#define N_ 32768
#define K_ 16
#define DIN_ 64
#define DOUT_ 64

typedef unsigned long long u64;

// Interleaved ping-pong state, 16B per (row, dim-pair):
//   word0 (u64): c as f32x2
//   word1 (u64): low u32 = h as f16x2, high u32 = G(=0.5*h@Uf) as f16x2
// Row 0 = zero row for masked children: .bss zero, never written.
__device__ u64 g_st[2][(N_ + 1) * 64];
// Precomputed Wx for all depths, f16x2 per dim-pair: [6*N][128], blocks f|i|u|o
__device__ uint32_t g_Wxh[(size_t)D_ * N_ * 128];
// Pre-swizzled split-bf16 weight planes (smem image): UAhi|UAlo|UFhi|UFlo
__device__ uint32_t g_Wpl[16384];
// software grid barrier
__device__ unsigned g_cnt;
__device__ unsigned g_gen;

#define HALF2 0x3F0000003F000000ULL   // {0.5f, 0.5f}

__device__ __forceinline__ u64 pk2(float lo, float hi) {
    u64 r; asm("mov.b64 %0, {%1,%2};" : "=l"(r) : "f"(lo), "f"(hi)); return r;
}
__device__ __forceinline__ void upk2(u64 v, float& lo, float& hi) {
    asm("mov.b64 {%0,%1}, %2;" : "=f"(lo), "=f"(hi) : "l"(v));
}
__device__ __forceinline__ u64 fma2_(u64 a, u64 b, u64 c) {
    u64 d; asm("fma.rn.f32x2 %0, %1, %2, %3;" : "=l"(d) : "l"(a), "l"(b), "l"(c)); return d;
}
__device__ __forceinline__ u64 add2_(u64 a, u64 b) {
    u64 d; asm("add.rn.f32x2 %0, %1, %2;" : "=l"(d) : "l"(a), "l"(b)); return d;
}
__device__ __forceinline__ u64 mul2_(u64 a, u64 b) {
    u64 d; asm("mul.rn.f32x2 %0, %1, %2;" : "=l"(d) : "l"(a), "l"(b)); return d;
}
__device__ __forceinline__ float tanha(float x) {
    float y; asm("tanh.approx.f32 %0, %1;" : "=f"(y) : "f"(x)); return y;
}
__device__ __forceinline__ u64 sig2h(u64 argHalf) {   // sigmoid(2*arg), arg pre-halved
    float a, b; upk2(argHalf, a, b);
    return fma2_(pk2(tanha(a), tanha(b)), HALF2, HALF2);
}
__device__ __forceinline__ u64 tanh2(u64 v) {
    float a, b; upk2(v, a, b);
    return pk2(tanha(a), tanha(b));
}
__device__ __forceinline__ uint32_t smem_u32(const void* p) {
    uint32_t a;
    asm("{ .reg .u64 t; cvta.to.shared.u64 t, %1; cvt.u32.u64 %0, t; }" : "=r"(a) : "l"(p));
    return a;
}
__device__ __forceinline__ uint32_t bf2pk(float lo, float hi) {
    uint32_t r;
    asm("cvt.rn.bf16x2.f32 %0, %1, %2;" : "=r"(r) : "f"(hi), "f"(lo));
    return r;
}
__device__ __forceinline__ uint32_t h2pk(float lo, float hi) {
    __half2 h = __float22half2_rn(make_float2(lo, hi));
    return *reinterpret_cast<uint32_t*>(&h);
}
__device__ __forceinline__ u64 h2up(uint32_t v) {   // f16x2 -> f32x2 (u64)
    __half2 h = *reinterpret_cast<__half2*>(&v);
    float2 f = __half22float2(h);
    return pk2(f.x, f.y);
}
#define SW128(off) ((off) ^ (((off) >> 3) & 0x70))

__device__ __forceinline__ void ldm_x4(uint32_t* r, uint32_t addr) {
    asm volatile("ldmatrix.sync.aligned.m8n8.x4.shared.b16 {%0,%1,%2,%3}, [%4];"
                 : "=r"(r[0]), "=r"(r[1]), "=r"(r[2]), "=r"(r[3]) : "r"(addr));
}
__device__ __forceinline__ void mma16816(float* c, const uint32_t* a,
                                         uint32_t b0, uint32_t b1) {
    asm volatile(
        "mma.sync.aligned.m16n8k16.row.col.f32.bf16.bf16.f32 "
        "{%0,%1,%2,%3}, {%4,%5,%6,%7}, {%8,%9}, {%0,%1,%2,%3};"
        : "+f"(c[0]), "+f"(c[1]), "+f"(c[2]), "+f"(c[3])
        : "r"(a[0]), "r"(a[1]), "r"(a[2]), "r"(a[3]), "r"(b0), "r"(b1));
}

// ======================= wx GEMM (+ fused weight-plane prep) ======================
#define WXA_HI 0
#define WXA_LO 16384
#define WXB_HI 32768
#define WXB_LO 49152
#define WX_SMEM 65536

__global__ __launch_bounds__(256) void wx_mma_kernel(const int* __restrict__ labels,
                                                     const float* __restrict__ E,
                                                     const float* __restrict__ Ww,
                                                     const float* __restrict__ Wb,
                                                     const float* __restrict__ Uf,
                                                     const float* __restrict__ Uiuo) {
    extern __shared__ char smc[];
    __shared__ int lab_s[128];
    uint32_t sb = smem_u32(smc);
    const int t = threadIdx.x;
    const int lane = t & 31, w = t >> 5;
    const int rowbase = (blockIdx.x >> 1) * 128;
    const int nb_g = (blockIdx.x & 1) * 128;

    // ---- fused prep: blocks 0-7 also build the node-kernel weight planes ----
    if (blockIdx.x < 8) {
        int idx0 = blockIdx.x * 256 + t;
        for (int idx = idx0; idx < 8192; idx += 2048) {
            if (idx < 6144) {
                int n = idx >> 5, kp = idx & 31;
                float x = Uiuo[(2 * kp) * 192 + n], y = Uiuo[(2 * kp + 1) * 192 + n];
                uint32_t hi = bf2pk(x, y);
                float rl = x - __uint_as_float(hi << 16);
                float rr = y - __uint_as_float(hi & 0xFFFF0000u);
                uint32_t lo = bf2pk(rl, rr);
                uint32_t off = SW128((uint32_t)(n * 128 + kp * 4)) >> 2;
                g_Wpl[off] = hi;
                g_Wpl[6144 + off] = lo;
            } else {
                int i = idx - 6144;
                int n = i >> 5, kp = i & 31;
                float x = 0.5f * Uf[(2 * kp) * 64 + n];
                float y = 0.5f * Uf[(2 * kp + 1) * 64 + n];
                uint32_t hi = bf2pk(x, y);
                float rl = x - __uint_as_float(hi << 16);
                float rr = y - __uint_as_float(hi & 0xFFFF0000u);
                uint32_t lo = bf2pk(rl, rr);
                uint32_t off = SW128((uint32_t)(n * 128 + kp * 4)) >> 2;
                g_Wpl[12288 + off] = hi;
                g_Wpl[14336 + off] = lo;
            }
        }
    }

    if (t < 128) lab_s[t] = labels[rowbase + t];
    __syncthreads();

#pragma unroll
    for (int i = 0; i < 8; i++) {
        int linear = i * 256 + t;
        int r = linear >> 4, f = linear & 15;
        float4 v = __ldg(reinterpret_cast<const float4*>(
                             E + (size_t)lab_s[r] * DIN_) + f);
        uint32_t h01 = bf2pk(v.x, v.y), h23 = bf2pk(v.z, v.w);
        float l0 = v.x - __uint_as_float(h01 << 16);
        float l1 = v.y - __uint_as_float(h01 & 0xFFFF0000u);
        float l2 = v.z - __uint_as_float(h23 << 16);
        float l3 = v.w - __uint_as_float(h23 & 0xFFFF0000u);
        uint32_t q01 = bf2pk(l0, l1), q23 = bf2pk(l2, l3);
        uint32_t off = SW128((uint32_t)(r * 128 + f * 8));
        *reinterpret_cast<u64*>(smc + WXA_HI + off) = ((u64)h23 << 32) | h01;
        *reinterpret_cast<u64*>(smc + WXA_LO + off) = ((u64)q23 << 32) | q01;
    }
#pragma unroll
    for (int i = 0; i < 16; i++) {
        int linear = i * 256 + t;
        int kp = linear >> 7, n = linear & 127;
        float w0 = __ldg(Ww + (2 * kp) * 256 + nb_g + n);
        float w1 = __ldg(Ww + (2 * kp + 1) * 256 + nb_g + n);
        uint32_t hp = bf2pk(w0, w1);
        float l0 = w0 - __uint_as_float(hp << 16);
        float l1 = w1 - __uint_as_float(hp & 0xFFFF0000u);
        uint32_t lp = bf2pk(l0, l1);
        uint32_t off = SW128((uint32_t)(n * 128 + kp * 4));
        *reinterpret_cast<uint32_t*>(smc + WXB_HI + off) = hp;
        *reinterpret_cast<uint32_t*>(smc + WXB_LO + off) = lp;
    }
    __syncthreads();

    const int mbase = 32 * (w & 3);
    const int nbase = 64 * (w >> 2);
    const int lrow = ((lane >> 3) & 1) * 8 + (lane & 7);
    const int lkb  = (lane >> 4) * 16;

    float acc[2][8][4];
#pragma unroll
    for (int mt = 0; mt < 2; mt++)
#pragma unroll
        for (int nt = 0; nt < 8; nt++)
#pragma unroll
            for (int e = 0; e < 4; e++) acc[mt][nt][e] = 0.f;

#pragma unroll
    for (int pass = 0; pass < 3; pass++) {
        const uint32_t Ab = sb + ((pass == 1) ? WXA_LO : WXA_HI);
        const uint32_t Bb = sb + ((pass == 2) ? WXB_LO : WXB_HI);
#pragma unroll
        for (int kc = 0; kc < 4; kc++) {
            const int koff = kc * 32 + lkb;
            uint32_t a[2][4];
#pragma unroll
            for (int mt = 0; mt < 2; mt++) {
                int r = mbase + 16 * mt + lrow;
                ldm_x4(a[mt], Ab + SW128((uint32_t)(r * 128 + koff)));
            }
#pragma unroll
            for (int tp = 0; tp < 4; tp++) {
                int n = nbase + tp * 16 + lrow;
                uint32_t b[4];
                ldm_x4(b, Bb + SW128((uint32_t)(n * 128 + koff)));
                mma16816(acc[0][2 * tp],     a[0], b[0], b[2]);
                mma16816(acc[0][2 * tp + 1], a[0], b[1], b[3]);
                mma16816(acc[1][2 * tp],     a[1], b[0], b[2]);
                mma16816(acc[1][2 * tp + 1], a[1], b[1], b[3]);
            }
        }
    }

    // epilogue: + bias, pack to f16x2, store u32 per dim-pair
    const int gid = lane >> 2, qc = lane & 3;
#pragma unroll
    for (int mt = 0; mt < 2; mt++) {
#pragma unroll
        for (int nt = 0; nt < 8; nt++) {
            int col = nb_g + nbase + nt * 8 + 2 * qc;
            float2 bia = __ldg(reinterpret_cast<const float2*>(Wb + col));
            int row0 = rowbase + mbase + 16 * mt + gid;
            g_Wxh[(size_t)row0 * 128 + (col >> 1)] =
                h2pk(acc[mt][nt][0] + bia.x, acc[mt][nt][1] + bia.y);
            g_Wxh[(size_t)(row0 + 8) * 128 + (col >> 1)] =
                h2pk(acc[mt][nt][2] + bia.x, acc[mt][nt][3] + bia.y);
        }
    }
}

// ========== fused node kernel: persistent over all 6 depths ======================
#define UA_HI 0
#define UA_LO 24576
#define UF_HI 49152
#define UF_LO 57344
#define AS_HI 65536
#define AS_LO 73728
#define BFOF  81920
#define NODE_SMEM 98816   // BF = 64 rows x 33 u64 (padded)
#define NODE_GRID 256

__global__ __launch_bounds__(256, 2) void node_all_kernel(const int* __restrict__ child_idx,
                                                          float* __restrict__ out) {
    extern __shared__ char smc[];
    const uint32_t sb = smem_u32(smc);
    const int tid = threadIdx.x, lane = tid & 31, w = tid >> 5;

    const unsigned gen0 = *((volatile unsigned*)&g_gen);

    // stage pre-built weight planes ONCE per CTA (persists across all depths)
    for (int i = tid; i < 4096; i += 256)
        reinterpret_cast<uint4*>(smc)[i] = __ldg(reinterpret_cast<const uint4*>(g_Wpl) + i);
    __syncthreads();

    u64* BF64 = reinterpret_cast<u64*>(smc + BFOF);
    const unsigned FULL = 0xffffffffu;
    const int g = lane >> 2, q = lane & 3;
    const int mrow = 16 * (w & 3), cg = w >> 2;
    const int lrow = ((lane >> 3) & 1) * 8 + (lane & 7);
    const int lkb  = (lane >> 4) * 16;

    for (int depth = 0; depth < D_; depth++) {
        const int rb = depth & 1;
        const u64* __restrict__ sp = g_st[rb];
        u64* __restrict__ sn = g_st[rb ^ 1];
        const size_t dN = (size_t)depth * N_;
        const bool last = (depth == D_ - 1);

        for (int ti = 0; ti < 2; ti++) {
            const int nb = (blockIdx.x * 2 + ti) * 64;

            // ================= phase 1: gather (LDG.128 per child) =================
            if (depth != 0) {
#pragma unroll
                for (int iter = 0; iter < 2; iter++) {
                    const int n0 = nb + 32 * iter + 4 * w;
                    int ci0 = child_idx[(dN + n0) * K_ + lane];
                    int ci1 = child_idx[(dN + n0) * K_ + 32 + lane];
                    u64 wfh[4], hs[4] = {0, 0, 0, 0}, bfa[4] = {0, 0, 0, 0};
#pragma unroll
                    for (int q4 = 0; q4 < 4; q4++)
                        wfh[q4] = mul2_(h2up(__ldg(g_Wxh + (dN + n0 + q4) * 128 + lane)),
                                        HALF2);
#pragma unroll 4
                    for (int k = 0; k < K_; k++) {
#pragma unroll
                        for (int q4 = 0; q4 < 4; q4++) {
                            int sl = q4 * 16 + k;
                            int c = (sl < 32) ? __shfl_sync(FULL, ci0, sl)
                                              : __shfl_sync(FULL, ci1, sl - 32);
                            ulonglong2 s = __ldg(reinterpret_cast<const ulonglong2*>(
                                                     sp + 2 * (c * 32 + lane)));
                            hs[q4] = add2_(hs[q4], h2up((uint32_t)s.y));
                            bfa[q4] = fma2_(s.x,
                                            sig2h(add2_(wfh[q4],
                                                        h2up((uint32_t)(s.y >> 32)))),
                                            bfa[q4]);
                        }
                    }
#pragma unroll
                    for (int q4 = 0; q4 < 4; q4++) {
                        int r = 32 * iter + 4 * w + q4;
                        float xl, xh; upk2(hs[q4], xl, xh);
                        uint32_t hi = bf2pk(xl, xh);
                        float rl = xl - __uint_as_float(hi << 16);
                        float rr = xh - __uint_as_float(hi & 0xFFFF0000u);
                        uint32_t lo = bf2pk(rl, rr);
                        uint32_t o = SW128((uint32_t)(r * 128 + 4 * lane));
                        *reinterpret_cast<uint32_t*>(smc + AS_HI + o) = hi;
                        *reinterpret_cast<uint32_t*>(smc + AS_LO + o) = lo;
                        BF64[r * 33 + lane] = bfa[q4];
                    }
                }
                __syncthreads();
            }

            // ================= phase 2: iuo = hs @ U_iuo =================
            float acc[3][4][4];
#pragma unroll
            for (int b = 0; b < 3; b++)
#pragma unroll
                for (int j4 = 0; j4 < 4; j4++)
#pragma unroll
                    for (int e = 0; e < 4; e++) acc[b][j4][e] = 0.f;

            if (depth != 0) {
#pragma unroll
                for (int pass = 0; pass < 3; pass++) {
                    const uint32_t Ab = sb + ((pass == 1) ? AS_LO : AS_HI);
                    const uint32_t Bb = sb + ((pass == 2) ? UA_LO : UA_HI);
#pragma unroll
                    for (int kc = 0; kc < 4; kc++) {
                        const int koff = kc * 32 + lkb;
                        uint32_t a[4];
                        ldm_x4(a, Ab + SW128((uint32_t)((mrow + lrow) * 128 + koff)));
#pragma unroll
                        for (int b = 0; b < 3; b++)
#pragma unroll
                            for (int tp = 0; tp < 2; tp++) {
                                int nrow = b * 64 + cg * 32 + tp * 16 + lrow;
                                uint32_t bb[4];
                                ldm_x4(bb, Bb + SW128((uint32_t)(nrow * 128 + koff)));
                                mma16816(acc[b][2 * tp],     a, bb[0], bb[2]);
                                mma16816(acc[b][2 * tp + 1], a, bb[1], bb[3]);
                            }
                    }
                }
            }

            // ================= phase 3: gates =================
            u64 nhv[4][2];
#pragma unroll
            for (int j4 = 0; j4 < 4; j4++) {
                const int dp = 16 * cg + 4 * j4 + q;
#pragma unroll
                for (int rh = 0; rh < 2; rh++) {
                    const int r = mrow + 8 * rh + g;
                    const uint32_t* wq = g_Wxh + (dN + nb + r) * 128;
                    u64 ai = pk2(acc[0][j4][2 * rh], acc[0][j4][2 * rh + 1]);
                    u64 au = pk2(acc[1][j4][2 * rh], acc[1][j4][2 * rh + 1]);
                    u64 ao = pk2(acc[2][j4][2 * rh], acc[2][j4][2 * rh + 1]);
                    u64 ig = sig2h(mul2_(add2_(ai, h2up(__ldg(wq + 32 + dp))), HALF2));
                    u64 ug = tanh2(add2_(au, h2up(__ldg(wq + 64 + dp))));
                    u64 og = sig2h(mul2_(add2_(ao, h2up(__ldg(wq + 96 + dp))), HALF2));
                    u64 bfv = (depth != 0) ? BF64[r * 33 + dp] : 0ULL;
                    u64 ncv = fma2_(ig, ug, bfv);
                    u64 nh = mul2_(og, tanh2(ncv));
                    nhv[j4][rh] = nh;
                    if (last) {
                        reinterpret_cast<u64*>(out)[(size_t)(nb + r) * 32 + dp] = nh;
                    } else {
                        sn[2 * ((size_t)(nb + r + 1) * 32 + dp)] = ncv;   // c word
                    }
                }
            }

            if (!last) {
                // ============ phase 4: stage new_h, G = 0.5*(new_h @ U_f) ============
                __syncthreads();
#pragma unroll
                for (int j4 = 0; j4 < 4; j4++) {
                    const int dp = 16 * cg + 4 * j4 + q;
#pragma unroll
                    for (int rh = 0; rh < 2; rh++) {
                        const int r = mrow + 8 * rh + g;
                        float xl, xh; upk2(nhv[j4][rh], xl, xh);
                        uint32_t hi = bf2pk(xl, xh);
                        float rl = xl - __uint_as_float(hi << 16);
                        float rr = xh - __uint_as_float(hi & 0xFFFF0000u);
                        uint32_t lo = bf2pk(rl, rr);
                        uint32_t o = SW128((uint32_t)(r * 128 + 4 * dp));
                        *reinterpret_cast<uint32_t*>(smc + AS_HI + o) = hi;
                        *reinterpret_cast<uint32_t*>(smc + AS_LO + o) = lo;
                    }
                }
                __syncthreads();

                float ga[4][4];
#pragma unroll
                for (int t2 = 0; t2 < 4; t2++)
#pragma unroll
                    for (int e = 0; e < 4; e++) ga[t2][e] = 0.f;

#pragma unroll
                for (int pass = 0; pass < 3; pass++) {
                    const uint32_t Ab = sb + ((pass == 1) ? AS_LO : AS_HI);
                    const uint32_t Bb = sb + ((pass == 2) ? UF_LO : UF_HI);
#pragma unroll
                    for (int kc = 0; kc < 4; kc++) {
                        const int koff = kc * 32 + lkb;
                        uint32_t a[4];
                        ldm_x4(a, Ab + SW128((uint32_t)((mrow + lrow) * 128 + koff)));
#pragma unroll
                        for (int tp = 0; tp < 2; tp++) {
                            int nrow = cg * 32 + tp * 16 + lrow;
                            uint32_t bb[4];
                            ldm_x4(bb, Bb + SW128((uint32_t)(nrow * 128 + koff)));
                            mma16816(ga[2 * tp],     a, bb[0], bb[2]);
                            mma16816(ga[2 * tp + 1], a, bb[1], bb[3]);
                        }
                    }
                }
#pragma unroll
                for (int tg = 0; tg < 4; tg++) {
                    const int dp = 16 * cg + 4 * tg + q;
#pragma unroll
                    for (int rh = 0; rh < 2; rh++) {
                        const int r = mrow + 8 * rh + g;
                        float xl, xh; upk2(nhv[tg][rh], xl, xh);
                        uint32_t hu = h2pk(xl, xh);
                        uint32_t gu = h2pk(ga[tg][2 * rh], ga[tg][2 * rh + 1]);
                        sn[2 * ((size_t)(nb + r + 1) * 32 + dp) + 1] =
                            ((u64)gu << 32) | hu;                       // hG word
                    }
                }
            }
            if (ti == 0) __syncthreads();
        }

        // ================= grid barrier between depths =================
        if (!last) {
            __syncthreads();
            if (tid == 0) {
                __threadfence();
                unsigned a = atomicAdd(&g_cnt, 1u);
                unsigned target = gen0 + (unsigned)depth + 1u;
                if ((a % NODE_GRID) == NODE_GRID - 1) {
                    atomicAdd(&g_gen, 1u);
                } else {
                    while (*((volatile unsigned*)&g_gen) < target) {}
                }
                __threadfence();
            }
            __syncthreads();
        }
    }
}

extern "C" void kernel_launch(void* const* d_in, const int* in_sizes, int n_in,
                              void* d_out, int out_size) {
    const int*   labels    = (const int*)d_in[0];
    const int*   child_idx = (const int*)d_in[1];
    const float* E         = (const float*)d_in[2];
    const float* Ww        = (const float*)d_in[3];
    const float* Wb        = (const float*)d_in[4];
    const float* Uf        = (const float*)d_in[5];
    const float* Uiuo      = (const float*)d_in[6];
    float*       out       = (float*)d_out;

    cudaFuncSetAttribute(node_all_kernel, cudaFuncAttributeMaxDynamicSharedMemorySize,
                         NODE_SMEM);
    cudaFuncSetAttribute(wx_mma_kernel, cudaFuncAttributeMaxDynamicSharedMemorySize,
                         WX_SMEM);

    wx_mma_kernel<<<(D_ * N_) / 128 * 2, 256, WX_SMEM>>>(labels, E, Ww, Wb, Uf, Uiuo);
    node_all_kernel<<<NODE_GRID, 256, NODE_SMEM>>>(child_idx, out);
}

// round 12
// speedup vs baseline: 1.5478x; 1.0906x over previous
#include <cuda_runtime.h>
#include <cuda_bf16.h>
#include <cuda_fp16.h>
#include <cstdint>

#define D_ 6
#define N_ 32768
#define K_ 16
#define DIN_ 64
#define DOUT_ 64

typedef unsigned long long u64;

// Interleaved ping-pong state, 16B per (row, dim-pair):
//   word0 (u64): c as f32x2
//   word1 (u64): low u32 = h as f16x2, high u32 = G(=0.5*h@Uf) as f16x2
// Row 0 = zero row for masked children: .bss zero, never written.
__device__ u64 g_st[2][(N_ + 1) * 64];
// Precomputed Wx for all depths, f16x2 per dim-pair: [6*N][128], blocks f|i|u|o
__device__ uint32_t g_Wxh[(size_t)D_ * N_ * 128];
// Pre-swizzled split-bf16 weight planes (node kernel): UAhi|UAlo|UFhi|UFlo
__device__ uint32_t g_Wpl[16384];
// Pre-swizzled split-bf16 W_w planes (wx kernel): [256n][64k] hi | lo
__device__ uint32_t g_Wxb[16384];
// software grid barrier
__device__ unsigned g_cnt;
__device__ unsigned g_gen;

#define HALF2 0x3F0000003F000000ULL   // {0.5f, 0.5f}

__device__ __forceinline__ u64 pk2(float lo, float hi) {
    u64 r; asm("mov.b64 %0, {%1,%2};" : "=l"(r) : "f"(lo), "f"(hi)); return r;
}
__device__ __forceinline__ void upk2(u64 v, float& lo, float& hi) {
    asm("mov.b64 {%0,%1}, %2;" : "=f"(lo), "=f"(hi) : "l"(v));
}
__device__ __forceinline__ u64 fma2_(u64 a, u64 b, u64 c) {
    u64 d; asm("fma.rn.f32x2 %0, %1, %2, %3;" : "=l"(d) : "l"(a), "l"(b), "l"(c)); return d;
}
__device__ __forceinline__ u64 add2_(u64 a, u64 b) {
    u64 d; asm("add.rn.f32x2 %0, %1, %2;" : "=l"(d) : "l"(a), "l"(b)); return d;
}
__device__ __forceinline__ u64 mul2_(u64 a, u64 b) {
    u64 d; asm("mul.rn.f32x2 %0, %1, %2;" : "=l"(d) : "l"(a), "l"(b)); return d;
}
__device__ __forceinline__ float tanha(float x) {
    float y; asm("tanh.approx.f32 %0, %1;" : "=f"(y) : "f"(x)); return y;
}
__device__ __forceinline__ u64 sig2h(u64 argHalf) {   // sigmoid(2*arg), arg pre-halved
    float a, b; upk2(argHalf, a, b);
    return fma2_(pk2(tanha(a), tanha(b)), HALF2, HALF2);
}
__device__ __forceinline__ u64 tanh2(u64 v) {
    float a, b; upk2(v, a, b);
    return pk2(tanha(a), tanha(b));
}
__device__ __forceinline__ uint32_t smem_u32(const void* p) {
    uint32_t a;
    asm("{ .reg .u64 t; cvta.to.shared.u64 t, %1; cvt.u32.u64 %0, t; }" : "=r"(a) : "l"(p));
    return a;
}
__device__ __forceinline__ uint32_t bf2pk(float lo, float hi) {
    uint32_t r;
    asm("cvt.rn.bf16x2.f32 %0, %1, %2;" : "=r"(r) : "f"(hi), "f"(lo));
    return r;
}
__device__ __forceinline__ uint32_t h2pk(float lo, float hi) {
    __half2 h = __float22half2_rn(make_float2(lo, hi));
    return *reinterpret_cast<uint32_t*>(&h);
}
__device__ __forceinline__ u64 h2up(uint32_t v) {   // f16x2 -> f32x2 (u64)
    __half2 h = *reinterpret_cast<__half2*>(&v);
    float2 f = __half22float2(h);
    return pk2(f.x, f.y);
}
#define SW128(off) ((off) ^ (((off) >> 3) & 0x70))

__device__ __forceinline__ void ldm_x4(uint32_t* r, uint32_t addr) {
    asm volatile("ldmatrix.sync.aligned.m8n8.x4.shared.b16 {%0,%1,%2,%3}, [%4];"
                 : "=r"(r[0]), "=r"(r[1]), "=r"(r[2]), "=r"(r[3]) : "r"(addr));
}
__device__ __forceinline__ void mma16816(float* c, const uint32_t* a,
                                         uint32_t b0, uint32_t b1) {
    asm volatile(
        "mma.sync.aligned.m16n8k16.row.col.f32.bf16.bf16.f32 "
        "{%0,%1,%2,%3}, {%4,%5,%6,%7}, {%8,%9}, {%0,%1,%2,%3};"
        : "+f"(c[0]), "+f"(c[1]), "+f"(c[2]), "+f"(c[3])
        : "r"(a[0]), "r"(a[1]), "r"(a[2]), "r"(a[3]), "r"(b0), "r"(b1));
}

__device__ __forceinline__ void split_store(float x, float y, uint32_t* hip,
                                            uint32_t* lop) {
    uint32_t hi = bf2pk(x, y);
    float rl = x - __uint_as_float(hi << 16);
    float rr = y - __uint_as_float(hi & 0xFFFF0000u);
    *hip = hi;
    *lop = bf2pk(rl, rr);
}

// ============ prep: build ALL static weight planes in global =====================
// g_Wpl: UAhi[6144) UAlo[6144) UFhi[2048) UFlo[2048)  (node kernel)
// g_Wxb: Whi[8192) Wlo[8192)  ([256n][64k] SW128, wx kernel)
__global__ void prep_kernel(const float* __restrict__ Uf,
                            const float* __restrict__ Uiuo,
                            const float* __restrict__ Ww) {
    int idx0 = blockIdx.x * 256 + threadIdx.x;
    for (int idx = idx0; idx < 16384; idx += 2048) {
        if (idx < 6144) {                 // U_iuo planes
            int n = idx >> 5, kp = idx & 31;
            float x = Uiuo[(2 * kp) * 192 + n], y = Uiuo[(2 * kp + 1) * 192 + n];
            uint32_t off = SW128((uint32_t)(n * 128 + kp * 4)) >> 2;
            split_store(x, y, g_Wpl + off, g_Wpl + 6144 + off);
        } else if (idx < 8192) {          // U_f planes (x0.5)
            int i = idx - 6144;
            int n = i >> 5, kp = i & 31;
            float x = 0.5f * Uf[(2 * kp) * 64 + n];
            float y = 0.5f * Uf[(2 * kp + 1) * 64 + n];
            uint32_t off = SW128((uint32_t)(n * 128 + kp * 4)) >> 2;
            split_store(x, y, g_Wpl + 12288 + off, g_Wpl + 14336 + off);
        } else {                          // W_w planes [256n][64k]
            int i = idx - 8192;
            int n = i >> 5, kp = i & 31;
            float x = Ww[(2 * kp) * 256 + n], y = Ww[(2 * kp + 1) * 256 + n];
            uint32_t off = SW128((uint32_t)(n * 128 + kp * 4)) >> 2;
            split_store(x, y, g_Wxb + off, g_Wxb + 8192 + off);
        }
    }
}

// ======================= wx GEMM: A staged once, both column halves ===============
#define WXA_HI 0
#define WXA_LO 16384
#define WXB_HI 32768
#define WXB_LO 49152
#define WX_SMEM 65536

__global__ __launch_bounds__(256) void wx_mma_kernel(const int* __restrict__ labels,
                                                     const float* __restrict__ E,
                                                     const float* __restrict__ Wb) {
    extern __shared__ char smc[];
    __shared__ int lab_s[128];
    uint32_t sb = smem_u32(smc);
    const int t = threadIdx.x;
    const int lane = t & 31, w = t >> 5;
    const int rowbase = blockIdx.x * 128;

    if (t < 128) lab_s[t] = labels[rowbase + t];
    __syncthreads();

    // ---- A: gather embeddings -> split-bf16 SW128 (once per CTA) ----
#pragma unroll
    for (int i = 0; i < 8; i++) {
        int linear = i * 256 + t;
        int r = linear >> 4, f = linear & 15;
        float4 v = __ldg(reinterpret_cast<const float4*>(
                             E + (size_t)lab_s[r] * DIN_) + f);
        uint32_t h01 = bf2pk(v.x, v.y), h23 = bf2pk(v.z, v.w);
        float l0 = v.x - __uint_as_float(h01 << 16);
        float l1 = v.y - __uint_as_float(h01 & 0xFFFF0000u);
        float l2 = v.z - __uint_as_float(h23 << 16);
        float l3 = v.w - __uint_as_float(h23 & 0xFFFF0000u);
        uint32_t q01 = bf2pk(l0, l1), q23 = bf2pk(l2, l3);
        uint32_t off = SW128((uint32_t)(r * 128 + f * 8));
        *reinterpret_cast<u64*>(smc + WXA_HI + off) = ((u64)h23 << 32) | h01;
        *reinterpret_cast<u64*>(smc + WXA_LO + off) = ((u64)q23 << 32) | q01;
    }

    const int mbase = 32 * (w & 3);
    const int nbase = 64 * (w >> 2);
    const int lrow = ((lane >> 3) & 1) * 8 + (lane & 7);
    const int lkb  = (lane >> 4) * 16;
    const int gid = lane >> 2, qc = lane & 3;

#pragma unroll
    for (int h = 0; h < 2; h++) {
        // ---- B: copy pre-built plane slices (16KB hi + 16KB lo) ----
        __syncthreads();   // half 1: ensure prior MMA reads done before overwrite
        {
            const uint4* src_h = reinterpret_cast<const uint4*>(g_Wxb) + h * 1024;
            const uint4* src_l = reinterpret_cast<const uint4*>(g_Wxb + 8192) + h * 1024;
            uint4* dst_h = reinterpret_cast<uint4*>(smc + WXB_HI);
            uint4* dst_l = reinterpret_cast<uint4*>(smc + WXB_LO);
#pragma unroll
            for (int i = 0; i < 4; i++) {
                dst_h[i * 256 + t] = __ldg(src_h + i * 256 + t);
                dst_l[i * 256 + t] = __ldg(src_l + i * 256 + t);
            }
        }
        __syncthreads();

        float acc[2][8][4];
#pragma unroll
        for (int mt = 0; mt < 2; mt++)
#pragma unroll
            for (int nt = 0; nt < 8; nt++)
#pragma unroll
                for (int e = 0; e < 4; e++) acc[mt][nt][e] = 0.f;

#pragma unroll
        for (int pass = 0; pass < 3; pass++) {
            const uint32_t Ab = sb + ((pass == 1) ? WXA_LO : WXA_HI);
            const uint32_t Bb = sb + ((pass == 2) ? WXB_LO : WXB_HI);
#pragma unroll
            for (int kc = 0; kc < 4; kc++) {
                const int koff = kc * 32 + lkb;
                uint32_t a[2][4];
#pragma unroll
                for (int mt = 0; mt < 2; mt++) {
                    int r = mbase + 16 * mt + lrow;
                    ldm_x4(a[mt], Ab + SW128((uint32_t)(r * 128 + koff)));
                }
#pragma unroll
                for (int tp = 0; tp < 4; tp++) {
                    int n = nbase + tp * 16 + lrow;
                    uint32_t b[4];
                    ldm_x4(b, Bb + SW128((uint32_t)(n * 128 + koff)));
                    mma16816(acc[0][2 * tp],     a[0], b[0], b[2]);
                    mma16816(acc[0][2 * tp + 1], a[0], b[1], b[3]);
                    mma16816(acc[1][2 * tp],     a[1], b[0], b[2]);
                    mma16816(acc[1][2 * tp + 1], a[1], b[1], b[3]);
                }
            }
        }

        // epilogue: + bias, pack to f16x2, store u32 per dim-pair
#pragma unroll
        for (int mt = 0; mt < 2; mt++) {
#pragma unroll
            for (int nt = 0; nt < 8; nt++) {
                int col = h * 128 + nbase + nt * 8 + 2 * qc;
                float2 bia = __ldg(reinterpret_cast<const float2*>(Wb + col));
                int row0 = rowbase + mbase + 16 * mt + gid;
                g_Wxh[(size_t)row0 * 128 + (col >> 1)] =
                    h2pk(acc[mt][nt][0] + bia.x, acc[mt][nt][1] + bia.y);
                g_Wxh[(size_t)(row0 + 8) * 128 + (col >> 1)] =
                    h2pk(acc[mt][nt][2] + bia.x, acc[mt][nt][3] + bia.y);
            }
        }
    }
}

// ========== fused node kernel: persistent over all 6 depths ======================
#define UA_HI 0
#define UA_LO 24576
#define UF_HI 49152
#define UF_LO 57344
#define AS_HI 65536
#define AS_LO 73728
#define BFOF  81920
#define NODE_SMEM 98816   // BF = 64 rows x 33 u64 (padded)
#define NODE_GRID 256

__global__ __launch_bounds__(256, 2) void node_all_kernel(const int* __restrict__ child_idx,
                                                          float* __restrict__ out) {
    extern __shared__ char smc[];
    const uint32_t sb = smem_u32(smc);
    const int tid = threadIdx.x, lane = tid & 31, w = tid >> 5;

    const unsigned gen0 = *((volatile unsigned*)&g_gen);

    // stage pre-built weight planes ONCE per CTA (persists across all depths)
    for (int i = tid; i < 4096; i += 256)
        reinterpret_cast<uint4*>(smc)[i] = __ldg(reinterpret_cast<const uint4*>(g_Wpl) + i);
    __syncthreads();

    u64* BF64 = reinterpret_cast<u64*>(smc + BFOF);
    const unsigned FULL = 0xffffffffu;
    const int g = lane >> 2, q = lane & 3;
    const int mrow = 16 * (w & 3), cg = w >> 2;
    const int lrow = ((lane >> 3) & 1) * 8 + (lane & 7);
    const int lkb  = (lane >> 4) * 16;

    for (int depth = 0; depth < D_; depth++) {
        const int rb = depth & 1;
        const u64* __restrict__ sp = g_st[rb];
        u64* __restrict__ sn = g_st[rb ^ 1];
        const size_t dN = (size_t)depth * N_;
        const bool last = (depth == D_ - 1);

        for (int ti = 0; ti < 2; ti++) {
            const int nb = (blockIdx.x * 2 + ti) * 64;

            // ================= phase 1: gather (LDG.128 per child) =================
            if (depth != 0) {
#pragma unroll
                for (int iter = 0; iter < 2; iter++) {
                    const int n0 = nb + 32 * iter + 4 * w;
                    int ci0 = child_idx[(dN + n0) * K_ + lane];
                    int ci1 = child_idx[(dN + n0) * K_ + 32 + lane];
                    u64 wfh[4], hs[4] = {0, 0, 0, 0}, bfa[4] = {0, 0, 0, 0};
#pragma unroll
                    for (int q4 = 0; q4 < 4; q4++)
                        wfh[q4] = mul2_(h2up(__ldg(g_Wxh + (dN + n0 + q4) * 128 + lane)),
                                        HALF2);
#pragma unroll 4
                    for (int k = 0; k < K_; k++) {
#pragma unroll
                        for (int q4 = 0; q4 < 4; q4++) {
                            int sl = q4 * 16 + k;
                            int c = (sl < 32) ? __shfl_sync(FULL, ci0, sl)
                                              : __shfl_sync(FULL, ci1, sl - 32);
                            ulonglong2 s = __ldg(reinterpret_cast<const ulonglong2*>(
                                                     sp + 2 * (c * 32 + lane)));
                            hs[q4] = add2_(hs[q4], h2up((uint32_t)s.y));
                            bfa[q4] = fma2_(s.x,
                                            sig2h(add2_(wfh[q4],
                                                        h2up((uint32_t)(s.y >> 32)))),
                                            bfa[q4]);
                        }
                    }
#pragma unroll
                    for (int q4 = 0; q4 < 4; q4++) {
                        int r = 32 * iter + 4 * w + q4;
                        float xl, xh; upk2(hs[q4], xl, xh);
                        uint32_t o = SW128((uint32_t)(r * 128 + 4 * lane));
                        split_store(xl, xh,
                                    reinterpret_cast<uint32_t*>(smc + AS_HI + o),
                                    reinterpret_cast<uint32_t*>(smc + AS_LO + o));
                        BF64[r * 33 + lane] = bfa[q4];
                    }
                }
                __syncthreads();
            }

            // ================= phase 2: iuo = hs @ U_iuo =================
            float acc[3][4][4];
#pragma unroll
            for (int b = 0; b < 3; b++)
#pragma unroll
                for (int j4 = 0; j4 < 4; j4++)
#pragma unroll
                    for (int e = 0; e < 4; e++) acc[b][j4][e] = 0.f;

            if (depth != 0) {
#pragma unroll
                for (int pass = 0; pass < 3; pass++) {
                    const uint32_t Ab = sb + ((pass == 1) ? AS_LO : AS_HI);
                    const uint32_t Bb = sb + ((pass == 2) ? UA_LO : UA_HI);
#pragma unroll
                    for (int kc = 0; kc < 4; kc++) {
                        const int koff = kc * 32 + lkb;
                        uint32_t a[4];
                        ldm_x4(a, Ab + SW128((uint32_t)((mrow + lrow) * 128 + koff)));
#pragma unroll
                        for (int b = 0; b < 3; b++)
#pragma unroll
                            for (int tp = 0; tp < 2; tp++) {
                                int nrow = b * 64 + cg * 32 + tp * 16 + lrow;
                                uint32_t bb[4];
                                ldm_x4(bb, Bb + SW128((uint32_t)(nrow * 128 + koff)));
                                mma16816(acc[b][2 * tp],     a, bb[0], bb[2]);
                                mma16816(acc[b][2 * tp + 1], a, bb[1], bb[3]);
                            }
                    }
                }
            }

            // ================= phase 3: gates =================
            u64 nhv[4][2];
#pragma unroll
            for (int j4 = 0; j4 < 4; j4++) {
                const int dp = 16 * cg + 4 * j4 + q;
#pragma unroll
                for (int rh = 0; rh < 2; rh++) {
                    const int r = mrow + 8 * rh + g;
                    const uint32_t* wq = g_Wxh + (dN + nb + r) * 128;
                    u64 ai = pk2(acc[0][j4][2 * rh], acc[0][j4][2 * rh + 1]);
                    u64 au = pk2(acc[1][j4][2 * rh], acc[1][j4][2 * rh + 1]);
                    u64 ao = pk2(acc[2][j4][2 * rh], acc[2][j4][2 * rh + 1]);
                    u64 ig = sig2h(mul2_(add2_(ai, h2up(__ldg(wq + 32 + dp))), HALF2));
                    u64 ug = tanh2(add2_(au, h2up(__ldg(wq + 64 + dp))));
                    u64 og = sig2h(mul2_(add2_(ao, h2up(__ldg(wq + 96 + dp))), HALF2));
                    u64 bfv = (depth != 0) ? BF64[r * 33 + dp] : 0ULL;
                    u64 ncv = fma2_(ig, ug, bfv);
                    u64 nh = mul2_(og, tanh2(ncv));
                    nhv[j4][rh] = nh;
                    if (last) {
                        reinterpret_cast<u64*>(out)[(size_t)(nb + r) * 32 + dp] = nh;
                    } else {
                        sn[2 * ((size_t)(nb + r + 1) * 32 + dp)] = ncv;   // c word
                    }
                }
            }

            if (!last) {
                // ============ phase 4: stage new_h, G = 0.5*(new_h @ U_f) ============
                __syncthreads();
#pragma unroll
                for (int j4 = 0; j4 < 4; j4++) {
                    const int dp = 16 * cg + 4 * j4 + q;
#pragma unroll
                    for (int rh = 0; rh < 2; rh++) {
                        const int r = mrow + 8 * rh + g;
                        float xl, xh; upk2(nhv[j4][rh], xl, xh);
                        uint32_t o = SW128((uint32_t)(r * 128 + 4 * dp));
                        split_store(xl, xh,
                                    reinterpret_cast<uint32_t*>(smc + AS_HI + o),
                                    reinterpret_cast<uint32_t*>(smc + AS_LO + o));
                    }
                }
                __syncthreads();

                float ga[4][4];
#pragma unroll
                for (int t2 = 0; t2 < 4; t2++)
#pragma unroll
                    for (int e = 0; e < 4; e++) ga[t2][e] = 0.f;

#pragma unroll
                for (int pass = 0; pass < 3; pass++) {
                    const uint32_t Ab = sb + ((pass == 1) ? AS_LO : AS_HI);
                    const uint32_t Bb = sb + ((pass == 2) ? UF_LO : UF_HI);
#pragma unroll
                    for (int kc = 0; kc < 4; kc++) {
                        const int koff = kc * 32 + lkb;
                        uint32_t a[4];
                        ldm_x4(a, Ab + SW128((uint32_t)((mrow + lrow) * 128 + koff)));
#pragma unroll
                        for (int tp = 0; tp < 2; tp++) {
                            int nrow = cg * 32 + tp * 16 + lrow;
                            uint32_t bb[4];
                            ldm_x4(bb, Bb + SW128((uint32_t)(nrow * 128 + koff)));
                            mma16816(ga[2 * tp],     a, bb[0], bb[2]);
                            mma16816(ga[2 * tp + 1], a, bb[1], bb[3]);
                        }
                    }
                }
#pragma unroll
                for (int tg = 0; tg < 4; tg++) {
                    const int dp = 16 * cg + 4 * tg + q;
#pragma unroll
                    for (int rh = 0; rh < 2; rh++) {
                        const int r = mrow + 8 * rh + g;
                        float xl, xh; upk2(nhv[tg][rh], xl, xh);
                        uint32_t hu = h2pk(xl, xh);
                        uint32_t gu = h2pk(ga[tg][2 * rh], ga[tg][2 * rh + 1]);
                        sn[2 * ((size_t)(nb + r + 1) * 32 + dp) + 1] =
                            ((u64)gu << 32) | hu;                       // hG word
                    }
                }
            }
            if (ti == 0) __syncthreads();
        }

        // ================= grid barrier between depths =================
        if (!last) {
            __syncthreads();
            if (tid == 0) {
                __threadfence();
                unsigned a = atomicAdd(&g_cnt, 1u);
                unsigned target = gen0 + (unsigned)depth + 1u;
                if ((a % NODE_GRID) == NODE_GRID - 1) {
                    atomicAdd(&g_gen, 1u);
                } else {
                    while (*((volatile unsigned*)&g_gen) < target) {}
                }
                __threadfence();
            }
            __syncthreads();
        }
    }
}

extern "C" void kernel_launch(void* const* d_in, const int* in_sizes, int n_in,
                              void* d_out, int out_size) {
    const int*   labels    = (const int*)d_in[0];
    const int*   child_idx = (const int*)d_in[1];
    const float* E         = (const float*)d_in[2];
    const float* Ww        = (const float*)d_in[3];
    const float* Wb        = (const float*)d_in[4];
    const float* Uf        = (const float*)d_in[5];
    const float* Uiuo      = (const float*)d_in[6];
    float*       out       = (float*)d_out;

    cudaFuncSetAttribute(node_all_kernel, cudaFuncAttributeMaxDynamicSharedMemorySize,
                         NODE_SMEM);
    cudaFuncSetAttribute(wx_mma_kernel, cudaFuncAttributeMaxDynamicSharedMemorySize,
                         WX_SMEM);

    prep_kernel<<<8, 256>>>(Uf, Uiuo, Ww);
    wx_mma_kernel<<<(D_ * N_) / 128, 256, WX_SMEM>>>(labels, E, Wb);
    node_all_kernel<<<NODE_GRID, 256, NODE_SMEM>>>(child_idx, out);
}